// round 10
// baseline (speedup 1.0000x reference)
#include <cuda_runtime.h>
#include <cuda_fp16.h>
#include <math.h>
#include <stdint.h>

// Shapes fixed: B=4, S=4096, D=1024
static constexpr int S_LEN = 4096;
static constexpr int D_DIM = 1024;
static constexpr int B_DIM = 4;
static constexpr int FD    = 4 * D_DIM;     // 4096
static constexpr int HD    = 2 * D_DIM;     // 2048
static constexpr int NROWS = B_DIM * S_LEN; // 16384
static constexpr int NDBLK = D_DIM / 32;    // 32 scan d-blocks

// ---------------- scratch (device globals; no allocs allowed) ----------------
__device__ __half g_xf  [(size_t)NROWS * D_DIM];   // 32 MB  x fp16
__device__ __half g_w0f [(size_t)D_DIM * D_DIM];   //  2 MB  W_omega*e fp16
__device__ __half g_omega[(size_t)NROWS * D_DIM];  // 32 MB  omega*e fp16
__device__ __half g_cf  [(size_t)NROWS * FD];      // 128 MB raw ctx fp16
__device__ __half g_w1g [(size_t)HD * FD];         // 16 MB  W1*gamma fp16
__device__ __half g_w2f [(size_t)D_DIM * HD];      //  4 MB  W2 fp16
__device__ __half g_h1f [(size_t)NROWS * HD];      // 64 MB  GELU output fp16
__device__ float  g_rs  [(size_t)NDBLK * NROWS];   //  2 MB  partial row sums
__device__ float  g_rs2 [(size_t)NDBLK * NROWS];   //  2 MB  partial row sumsq
__device__ float  g_mu  [NROWS];
__device__ float  g_inv [NROWS];
__device__ float  g_r1  [HD];                      // sum_d gamma*W1
__device__ float  g_r2  [HD];                      // sum_d beta*W1
__device__ float  g_e   [D_DIM];                   // exp(log_scale)
__device__ float  g_b0s [D_DIM];                   // b_omega * e

// ---------------- PTX helpers (stable ISA only) ----------------
__device__ __forceinline__ uint32_t smem_u32(const void* p) {
    uint32_t a;
    asm("{ .reg .u64 t; cvta.to.shared.u64 t, %1; cvt.u32.u64 %0, t; }" : "=r"(a) : "l"(p));
    return a;
}
__device__ __forceinline__ void cp_async16(uint32_t saddr, const void* gptr) {
    asm volatile("cp.async.cg.shared.global [%0], [%1], 16;" :: "r"(saddr), "l"(gptr));
}
__device__ __forceinline__ void cp_commit() { asm volatile("cp.async.commit_group;" ::: "memory"); }
template <int N> __device__ __forceinline__ void cp_wait() {
    asm volatile("cp.async.wait_group %0;" :: "n"(N) : "memory");
}

#define LDMX4(r0, r1, r2, r3, addr)                                              \
    asm volatile("ldmatrix.sync.aligned.m8n8.x4.shared.b16 {%0,%1,%2,%3}, [%4];" \
        : "=r"(r0), "=r"(r1), "=r"(r2), "=r"(r3) : "r"(addr))

#define MMA16816_F16(d, a, b0, b1)                                               \
    asm volatile("mma.sync.aligned.m16n8k16.row.col.f32.f16.f16.f32 "            \
        "{%0,%1,%2,%3}, {%4,%5,%6,%7}, {%8,%9}, {%0,%1,%2,%3};"                  \
        : "+f"((d)[0]), "+f"((d)[1]), "+f"((d)[2]), "+f"((d)[3])                 \
        : "r"((a)[0]), "r"((a)[1]), "r"((a)[2]), "r"((a)[3]), "r"(b0), "r"(b1))

// ===========================================================================
// fp16 GEMM (f32 accum): C[M,N] = A[M,K]*B[N,K]^T.
// 128x128 block tile, BK=64, 3-stage cp.async.
// 128 threads (4 warps, 2x2), warp tile 64x64: MMA:LDSM = 32:8 per K16 step
// (vs 16:6 before) -> fewer shared reads + less address math per MMA.
// 2 CTAs/SM (regs ~190*128 = 24.3K/CTA, smem 96KB/CTA).
// EPI 0: + bias           -> f16 out            (GEMM1: omega)
// EPI 1: LN-affine + GELU -> f16 out            (GEMM2, fused LayerNorm)
// EPI 2: + bias + res     -> fp32 out           (GEMM3, residual)
// ===========================================================================
static constexpr int TILE_B    = 128 * 128;           // 16 KB f16 128x64 tile
static constexpr int STAGE_BF  = 2 * TILE_B;          // 32 KB
static constexpr int NSTAGEF   = 3;
static constexpr int GEMM_DSMF = NSTAGEF * STAGE_BF;  // 96 KB -> 2 CTAs/SM

template <int EPI>
__global__ __launch_bounds__(128, 2)
void gemm_f16_kernel(const __half* __restrict__ A, const __half* __restrict__ B,
                     const float* __restrict__ bias, const float* __restrict__ res,
                     const float* __restrict__ mu, const float* __restrict__ inv,
                     const float* __restrict__ r1, const float* __restrict__ r2,
                     float* __restrict__ outf, __half* __restrict__ outh,
                     int M, int N, int K)
{
    extern __shared__ __align__(1024) unsigned char dsm[];
    const int tid = threadIdx.x;
    const int wid = tid >> 5;
    const int lid = tid & 31;
    const int m0 = blockIdx.y * 128;
    const int n0 = blockIdx.x * 128;
    const uint32_t dsm_b = smem_u32(dsm);

    const int warpM = wid >> 1;          // 0..1 (64-row strip)
    const int warpN = wid & 1;           // 0..1 (64-col strip)
    const int rl = lid & 15, chh = lid >> 4;

    const __half* At = A + (size_t)m0 * K;
    const __half* Bt = B + (size_t)n0 * K;

    const int nchunk = K >> 6;

    auto load_chunk = [&](int chunk) {
        const uint32_t sb = dsm_b + (chunk % NSTAGEF) * STAGE_BF;
        const int koff = chunk << 6;
        #pragma unroll
        for (int i = 0; i < 16; i++) {
            const int u = i * 128 + tid;           // 0..2047
            const int t = u >> 10;                 // 0=A, 1=B
            const int v = u & 1023;
            const int row = v >> 3, c = v & 7;
            const __half* g = t ? Bt : At;
            const void* gp = g + (size_t)row * K + koff + c * 8;
            const uint32_t sa = sb + t * TILE_B + row * 128 + ((c ^ (row & 7)) << 4);
            cp_async16(sa, gp);
        }
        cp_commit();
    };

    float acc[4][8][4];
    #pragma unroll
    for (int mi = 0; mi < 4; mi++)
        #pragma unroll
        for (int ni = 0; ni < 8; ni++)
            #pragma unroll
            for (int r = 0; r < 4; r++) acc[mi][ni][r] = 0.0f;

    load_chunk(0);
    load_chunk(1);

    for (int c = 0; c < nchunk; c++) {
        if (c < nchunk - 1) cp_wait<1>(); else cp_wait<0>();
        __syncthreads();
        if (c + 2 < nchunk) load_chunk(c + 2);

        const uint32_t st = dsm_b + (c % NSTAGEF) * STAGE_BF;
        #pragma unroll
        for (int ks = 0; ks < 4; ks++) {
            const int kchunk = (ks << 1) | chh;
            uint32_t a[4][4], b[4][4];
            #pragma unroll
            for (int mi = 0; mi < 4; mi++) {
                const int row = warpM * 64 + mi * 16 + rl;
                const uint32_t ad = st + row * 128 + ((kchunk ^ (row & 7)) << 4);
                LDMX4(a[mi][0], a[mi][1], a[mi][2], a[mi][3], ad);
            }
            #pragma unroll
            for (int nj = 0; nj < 4; nj++) {
                const int row = warpN * 64 + nj * 16 + rl;
                const uint32_t bd = st + TILE_B + row * 128 + ((kchunk ^ (row & 7)) << 4);
                LDMX4(b[nj][0], b[nj][1], b[nj][2], b[nj][3], bd);
            }
            #pragma unroll
            for (int mi = 0; mi < 4; mi++)
                #pragma unroll
                for (int ni = 0; ni < 8; ni++) {
                    const int nj = ni >> 1, sel = ni & 1;
                    MMA16816_F16(acc[mi][ni], a[mi], b[nj][sel], b[nj][2 + sel]);
                }
        }
    }

    const int g = lid >> 2, q = lid & 3;
    #pragma unroll
    for (int mi = 0; mi < 4; mi++)
        #pragma unroll
        for (int ni = 0; ni < 8; ni++) {
            const int row = m0 + warpM * 64 + mi * 16 + g;
            const int col = n0 + warpN * 64 + ni * 8 + q * 2;
            const size_t o0 = (size_t)row * N + col;
            const size_t o1 = (size_t)(row + 8) * N + col;
            float v[4];
            if (EPI == 1) {
                // fused LayerNorm affine: inv*acc - inv*mu*r1[n] + r2[n] + bias[n]
                const float2 rr1 = *(const float2*)(r1 + col);
                const float2 rr2 = *(const float2*)(r2 + col);
                const float2 bb  = *(const float2*)(bias + col);
                const float i0 = inv[row],     m0v = mu[row];
                const float i1 = inv[row + 8], m1v = mu[row + 8];
                v[0] = i0 * acc[mi][ni][0] - i0 * m0v * rr1.x + rr2.x + bb.x;
                v[1] = i0 * acc[mi][ni][1] - i0 * m0v * rr1.y + rr2.y + bb.y;
                v[2] = i1 * acc[mi][ni][2] - i1 * m1v * rr1.x + rr2.x + bb.x;
                v[3] = i1 * acc[mi][ni][3] - i1 * m1v * rr1.y + rr2.y + bb.y;
                #pragma unroll
                for (int r = 0; r < 4; r++)
                    v[r] = 0.5f * v[r] * (1.0f + erff(v[r] * 0.70710678118654752f));
                *(__half2*)(outh + o0) = __floats2half2_rn(v[0], v[1]);
                *(__half2*)(outh + o1) = __floats2half2_rn(v[2], v[3]);
            } else {
                const float2 bb = *(const float2*)(bias + col);
                v[0] = acc[mi][ni][0] + bb.x;
                v[1] = acc[mi][ni][1] + bb.y;
                v[2] = acc[mi][ni][2] + bb.x;
                v[3] = acc[mi][ni][3] + bb.y;
                if (EPI == 2) {
                    const float2 q0 = *(const float2*)(res + o0);
                    const float2 q1 = *(const float2*)(res + o1);
                    *(float2*)(outf + o0) = make_float2(v[0] + q0.x, v[1] + q0.y);
                    *(float2*)(outf + o1) = make_float2(v[2] + q1.x, v[3] + q1.y);
                } else {
                    *(__half2*)(outh + o0) = __floats2half2_rn(v[0], v[1]);
                    *(__half2*)(outh + o1) = __floats2half2_rn(v[2], v[3]);
                }
            }
        }
}

// ---------------------------------------------------------------------------
// escale: e = exp(log_scale), b0s = b_omega * e
// ---------------------------------------------------------------------------
__global__ __launch_bounds__(256)
void escale_kernel(const float* __restrict__ log_scale, const float* __restrict__ b0,
                   float* __restrict__ e, float* __restrict__ b0s)
{
    const int i = blockIdx.x * blockDim.x + threadIdx.x;
    if (i >= D_DIM) return;
    const float ev = expf(log_scale[i]);
    e[i] = ev;
    b0s[i] = b0[i] * ev;
}

// ---------------------------------------------------------------------------
// Fused operand prep (segments): x->xf | W0*e->w0f | W1*gamma->w1g | W2->w2f
// ---------------------------------------------------------------------------
static constexpr int PREP_B0 = NROWS * D_DIM / 1024;                 // 16384
static constexpr int PREP_B1 = PREP_B0 + D_DIM * D_DIM / 1024;       // +1024
static constexpr int PREP_B2 = PREP_B1 + HD * FD / 1024;             // +8192
static constexpr int PREP_B3 = PREP_B2 + D_DIM * HD / 1024;          // +2048

__global__ __launch_bounds__(256)
void prep_kernel(const float* __restrict__ x, const float* __restrict__ W0,
                 const float* __restrict__ W1, const float* __restrict__ W2,
                 const float* __restrict__ gamma, const float* __restrict__ e,
                 __half* __restrict__ xf, __half* __restrict__ w0f,
                 __half* __restrict__ w1g, __half* __restrict__ w2f)
{
    const int blk = blockIdx.x;
    const int tid = threadIdx.x;
    if (blk < PREP_B0) {
        const size_t i = (size_t)blk * 256 + tid;     // float4 index
        const float4 v = ((const float4*)x)[i];
        __half2* op = (__half2*)xf;
        op[2 * i]     = __floats2half2_rn(v.x, v.y);
        op[2 * i + 1] = __floats2half2_rn(v.z, v.w);
    } else if (blk < PREP_B1) {
        const size_t i = (size_t)(blk - PREP_B0) * 256 + tid;
        const int n = (int)((i * 4) >> 10);           // row (K=1024 fast)
        const float ev = e[n];
        const float4 v = ((const float4*)W0)[i];
        __half2* op = (__half2*)w0f;
        op[2 * i]     = __floats2half2_rn(v.x * ev, v.y * ev);
        op[2 * i + 1] = __floats2half2_rn(v.z * ev, v.w * ev);
    } else if (blk < PREP_B2) {
        const size_t i = (size_t)(blk - PREP_B1) * 256 + tid;
        const int d = (int)((i * 4) & (FD - 1));
        const float4 v = ((const float4*)W1)[i];
        const float4 gg = *(const float4*)(gamma + d);
        __half2* op = (__half2*)w1g;
        op[2 * i]     = __floats2half2_rn(v.x * gg.x, v.y * gg.y);
        op[2 * i + 1] = __floats2half2_rn(v.z * gg.z, v.w * gg.w);
    } else {
        const size_t i = (size_t)(blk - PREP_B2) * 256 + tid;
        const float4 v = ((const float4*)W2)[i];
        __half2* op = (__half2*)w2f;
        op[2 * i]     = __floats2half2_rn(v.x, v.y);
        op[2 * i + 1] = __floats2half2_rn(v.z, v.w);
    }
}

// r1[n] = sum_d gamma[d]*W1[n,d];  r2[n] = sum_d beta[d]*W1[n,d]. One warp per n.
__global__ __launch_bounds__(256)
void r12_kernel(const float* __restrict__ W1, const float* __restrict__ gamma,
                const float* __restrict__ beta, float* __restrict__ r1,
                float* __restrict__ r2)
{
    const int n = blockIdx.x * 8 + threadIdx.y;
    const int lane = threadIdx.x;
    const float* wr = W1 + (size_t)n * FD;
    float a = 0.0f, b = 0.0f;
    for (int d = lane * 4; d < FD; d += 128) {
        const float4 w = *(const float4*)(wr + d);
        const float4 gg = *(const float4*)(gamma + d);
        const float4 be = *(const float4*)(beta + d);
        a += w.x * gg.x + w.y * gg.y + w.z * gg.z + w.w * gg.w;
        b += w.x * be.x + w.y * be.y + w.z * be.z + w.w * be.w;
    }
    #pragma unroll
    for (int off = 16; off > 0; off >>= 1) {
        a += __shfl_down_sync(0xffffffffu, a, off);
        b += __shfl_down_sync(0xffffffffu, b, off);
    }
    if (lane == 0) { r1[n] = a; r2[n] = b; }
}

// finalize per-row LN stats from 32 deterministic partials
__global__ __launch_bounds__(256)
void rowstat_kernel(const float* __restrict__ rs, const float* __restrict__ rs2,
                    float* __restrict__ mu, float* __restrict__ inv)
{
    const int r = blockIdx.x * blockDim.x + threadIdx.x;
    if (r >= NROWS) return;
    float s1 = 0.0f, s2 = 0.0f;
    #pragma unroll
    for (int j = 0; j < NDBLK; j++) {
        s1 += rs [(size_t)j * NROWS + r];
        s2 += rs2[(size_t)j * NROWS + r];
    }
    const float m = s1 * (1.0f / FD);
    mu[r]  = m;
    inv[r] = rsqrtf(s2 * (1.0f / FD) - m * m + 1e-5f);
}

// ---------------------------------------------------------------------------
// Fused sequential scans -> raw ctx fp16 + deterministic per-row partial sums
// ---------------------------------------------------------------------------
__global__ __launch_bounds__(1024)
void scan_kernel(const __half* __restrict__ xf, const __half* __restrict__ omega,
                 __half* __restrict__ ctx,
                 float* __restrict__ rs, float* __restrict__ rs2)
{
    __shared__ float xs[32][33];
    __shared__ float os[32][33];
    __shared__ float ob[4][32][33];

    const int b  = blockIdx.y;
    const int dblk = blockIdx.x;
    const int d0 = dblk * 32;
    const int tx = threadIdx.x;
    const int ty = threadIdx.y;

    const __half* xp = xf    + (size_t)b * S_LEN * D_DIM;
    const __half* op = omega + (size_t)b * S_LEN * D_DIM;
    __half*      cp = ctx   + (size_t)b * S_LEN * FD;
    const int rowbase = b * S_LEN;

    float c0 = 0.0f, c1 = 0.0f, c2 = 0.0f;

    for (int s0 = 0; s0 < S_LEN; s0 += 32) {
        xs[ty][tx] = __half2float(xp[(size_t)(s0 + ty) * D_DIM + d0 + tx]);
        os[ty][tx] = __half2float(op[(size_t)(s0 + ty) * D_DIM + d0 + tx]);
        __syncthreads();

        const float pos = (float)(s0 + tx + 1);
        float w = os[tx][ty] * rsqrtf(pos);

        float pl = w;
        #pragma unroll
        for (int off = 1; off < 32; off <<= 1) {
            float t = __shfl_up_sync(0xffffffffu, pl, off);
            if (tx >= off) pl += t;
        }
        const float phi = c0 + pl;
        c0 += __shfl_sync(0xffffffffu, pl, 31);

        float sv, cv;
        sincosf(phi, &sv, &cv);
        const float xv  = xs[tx][ty];
        const float cmr = xv * cv;
        const float cmi = xv * sv;

        float pr = cmr;
        #pragma unroll
        for (int off = 1; off < 32; off <<= 1) {
            float t = __shfl_up_sync(0xffffffffu, pr, off);
            if (tx >= off) pr += t;
        }
        float pi = cmi;
        #pragma unroll
        for (int off = 1; off < 32; off <<= 1) {
            float t = __shfl_up_sync(0xffffffffu, pi, off);
            if (tx >= off) pi += t;
        }

        const float memr = (c1 + pr) / pos;
        const float memi = (c2 + pi) / pos;
        c1 += __shfl_sync(0xffffffffu, pr, 31);
        c2 += __shfl_sync(0xffffffffu, pi, 31);

        const float retr = memr * cv + memi * sv;
        const float reti = memi * cv - memr * sv;

        ob[0][tx][ty] = cmr;
        ob[1][tx][ty] = cmi;
        ob[2][tx][ty] = retr;
        ob[3][tx][ty] = reti;
        __syncthreads();

        // store phase: thread (tx=d-local=lane, ty=s-local=warp)
        const float v0 = ob[0][ty][tx];
        const float v1 = ob[1][ty][tx];
        const float v2 = ob[2][ty][tx];
        const float v3 = ob[3][ty][tx];
        const size_t ro = (size_t)(s0 + ty) * FD + d0 + tx;
        cp[ro]             = __float2half(v0);
        cp[ro + D_DIM]     = __float2half(v1);
        cp[ro + 2 * D_DIM] = __float2half(v2);
        cp[ro + 3 * D_DIM] = __float2half(v3);

        // deterministic per-row partial sums over this block's 32 channels
        float ls  = v0 + v1 + v2 + v3;
        float ls2 = v0 * v0 + v1 * v1 + v2 * v2 + v3 * v3;
        #pragma unroll
        for (int off = 16; off > 0; off >>= 1) {
            ls  += __shfl_down_sync(0xffffffffu, ls,  off);
            ls2 += __shfl_down_sync(0xffffffffu, ls2, off);
        }
        if (tx == 0) {
            const size_t pidx = (size_t)dblk * NROWS + rowbase + s0 + ty;
            rs [pidx] = ls;
            rs2[pidx] = ls2;
        }
        __syncthreads();
    }
}

// ---------------------------------------------------------------------------
extern "C" void kernel_launch(void* const* d_in, const int* in_sizes, int n_in,
                              void* d_out, int out_size)
{
    const float* x         = (const float*)d_in[0];
    const float* W_omega   = (const float*)d_in[1];
    const float* b_omega   = (const float*)d_in[2];
    const float* log_scale = (const float*)d_in[3];
    const float* ln_gamma  = (const float*)d_in[4];
    const float* ln_beta   = (const float*)d_in[5];
    const float* W1        = (const float*)d_in[6];
    const float* b1        = (const float*)d_in[7];
    const float* W2        = (const float*)d_in[8];
    const float* b2        = (const float*)d_in[9];
    float* out = (float*)d_out;

    __half *xf, *w0f, *omega_p, *cf, *w1g, *w2f, *h1f;
    float *rs, *rs2, *mu, *inv, *r1, *r2, *e, *b0s;
    cudaGetSymbolAddress((void**)&xf,      g_xf);
    cudaGetSymbolAddress((void**)&w0f,     g_w0f);
    cudaGetSymbolAddress((void**)&omega_p, g_omega);
    cudaGetSymbolAddress((void**)&cf,      g_cf);
    cudaGetSymbolAddress((void**)&w1g,     g_w1g);
    cudaGetSymbolAddress((void**)&w2f,     g_w2f);
    cudaGetSymbolAddress((void**)&h1f,     g_h1f);
    cudaGetSymbolAddress((void**)&rs,      g_rs);
    cudaGetSymbolAddress((void**)&rs2,     g_rs2);
    cudaGetSymbolAddress((void**)&mu,      g_mu);
    cudaGetSymbolAddress((void**)&inv,     g_inv);
    cudaGetSymbolAddress((void**)&r1,      g_r1);
    cudaGetSymbolAddress((void**)&r2,      g_r2);
    cudaGetSymbolAddress((void**)&e,       g_e);
    cudaGetSymbolAddress((void**)&b0s,     g_b0s);

    cudaFuncSetAttribute(gemm_f16_kernel<0>, cudaFuncAttributeMaxDynamicSharedMemorySize, GEMM_DSMF);
    cudaFuncSetAttribute(gemm_f16_kernel<1>, cudaFuncAttributeMaxDynamicSharedMemorySize, GEMM_DSMF);
    cudaFuncSetAttribute(gemm_f16_kernel<2>, cudaFuncAttributeMaxDynamicSharedMemorySize, GEMM_DSMF);

    // operand prep
    escale_kernel<<<(D_DIM + 255) / 256, 256>>>(log_scale, b_omega, e, b0s);
    prep_kernel<<<PREP_B3, 256>>>(x, W_omega, W1, W2, ln_gamma, e, xf, w0f, w1g, w2f);
    r12_kernel<<<HD / 8, dim3(32, 8)>>>(W1, ln_gamma, ln_beta, r1, r2);

    // 1) omega*e = x @ (W_omega*e)^T + b_omega*e   (fp16, f16 out)
    gemm_f16_kernel<0><<<dim3(D_DIM / 128, NROWS / 128), 128, GEMM_DSMF>>>(
        xf, w0f, b0s, nullptr, nullptr, nullptr, nullptr, nullptr,
        nullptr, omega_p, NROWS, D_DIM, D_DIM);

    // 2) scans -> raw ctx f16 + LN partial sums
    scan_kernel<<<dim3(NDBLK, B_DIM), dim3(32, 32)>>>(xf, omega_p, cf, rs, rs2);

    // 3) finalize per-row mu, inv
    rowstat_kernel<<<(NROWS + 255) / 256, 256>>>(rs, rs2, mu, inv);

    // 4) h1 = GELU(LN-affine(ctx @ (W1*gamma)^T)) -> f16   (LayerNorm fused)
    gemm_f16_kernel<1><<<dim3(HD / 128, NROWS / 128), 128, GEMM_DSMF>>>(
        cf, w1g, b1, nullptr, mu, inv, r1, r2,
        nullptr, h1f, NROWS, HD, FD);

    // 5) out = x + h1 @ W2^T + b2
    gemm_f16_kernel<2><<<dim3(D_DIM / 128, NROWS / 128), 128, GEMM_DSMF>>>(
        h1f, w2f, b2, x, nullptr, nullptr, nullptr, nullptr,
        out, nullptr, NROWS, D_DIM, HD);
}

// round 11
// speedup vs baseline: 1.0316x; 1.0316x over previous
#include <cuda_runtime.h>
#include <cuda_fp16.h>
#include <math.h>
#include <stdint.h>

// Shapes fixed: B=4, S=4096, D=1024
static constexpr int S_LEN = 4096;
static constexpr int D_DIM = 1024;
static constexpr int B_DIM = 4;
static constexpr int FD    = 4 * D_DIM;     // 4096
static constexpr int HD    = 2 * D_DIM;     // 2048
static constexpr int NROWS = B_DIM * S_LEN; // 16384
static constexpr int NDBLK = D_DIM / 32;    // 32 scan d-blocks

// ---------------- scratch (device globals; no allocs allowed) ----------------
__device__ __half g_xf  [(size_t)NROWS * D_DIM];   // 32 MB  x fp16
__device__ __half g_w0f [(size_t)D_DIM * D_DIM];   //  2 MB  W_omega*e fp16
__device__ __half g_omega[(size_t)NROWS * D_DIM];  // 32 MB  omega*e fp16
__device__ __half g_cf  [(size_t)NROWS * FD];      // 128 MB raw ctx fp16
__device__ __half g_w1g [(size_t)HD * FD];         // 16 MB  W1*gamma fp16
__device__ __half g_w2f [(size_t)D_DIM * HD];      //  4 MB  W2 fp16
__device__ __half g_h1f [(size_t)NROWS * HD];      // 64 MB  GELU output fp16
__device__ float  g_rs  [(size_t)NDBLK * NROWS];   //  2 MB  partial row sums
__device__ float  g_rs2 [(size_t)NDBLK * NROWS];   //  2 MB  partial row sumsq
__device__ float  g_mu  [NROWS];
__device__ float  g_inv [NROWS];
__device__ float  g_r1  [HD];                      // sum_d gamma*W1
__device__ float  g_r2  [HD];                      // sum_d beta*W1
__device__ float  g_e   [D_DIM];                   // exp(log_scale)
__device__ float  g_b0s [D_DIM];                   // b_omega * e

// ---------------- PTX helpers (stable ISA only) ----------------
__device__ __forceinline__ uint32_t smem_u32(const void* p) {
    uint32_t a;
    asm("{ .reg .u64 t; cvta.to.shared.u64 t, %1; cvt.u32.u64 %0, t; }" : "=r"(a) : "l"(p));
    return a;
}
__device__ __forceinline__ void cp_async16(uint32_t saddr, const void* gptr) {
    asm volatile("cp.async.cg.shared.global [%0], [%1], 16;" :: "r"(saddr), "l"(gptr));
}
__device__ __forceinline__ void cp_commit() { asm volatile("cp.async.commit_group;" ::: "memory"); }
template <int N> __device__ __forceinline__ void cp_wait() {
    asm volatile("cp.async.wait_group %0;" :: "n"(N) : "memory");
}

#define LDMX4(r0, r1, r2, r3, addr)                                              \
    asm volatile("ldmatrix.sync.aligned.m8n8.x4.shared.b16 {%0,%1,%2,%3}, [%4];" \
        : "=r"(r0), "=r"(r1), "=r"(r2), "=r"(r3) : "r"(addr))

#define MMA16816_F16(d, a, b0, b1)                                               \
    asm volatile("mma.sync.aligned.m16n8k16.row.col.f32.f16.f16.f32 "            \
        "{%0,%1,%2,%3}, {%4,%5,%6,%7}, {%8,%9}, {%0,%1,%2,%3};"                  \
        : "+f"((d)[0]), "+f"((d)[1]), "+f"((d)[2]), "+f"((d)[3])                 \
        : "r"((a)[0]), "r"((a)[1]), "r"((a)[2]), "r"((a)[3]), "r"(b0), "r"(b1))

// ===========================================================================
// fp16 GEMM (f32 accum): C[M,N] = A[M,K]*B[N,K]^T.  (R8 best-measured config)
// 128x128 tile, BK=64, 3-stage cp.async, 256 thr (8 warps 2x4), warp 64x32.
// 2 CTAs/SM (128 regs * 256 thr * 2 = 64K).
// EPI 0: + bias           -> f16 out            (GEMM1: omega)
// EPI 1: LN-affine + GELU -> f16 out            (GEMM2, fused LayerNorm)
// EPI 2: + bias + res     -> fp32 out           (GEMM3, residual)
// ===========================================================================
static constexpr int TILE_B    = 128 * 128;           // 16 KB f16 128x64 tile
static constexpr int STAGE_BF  = 2 * TILE_B;          // 32 KB
static constexpr int NSTAGEF   = 3;
static constexpr int GEMM_DSMF = NSTAGEF * STAGE_BF;  // 96 KB -> 2 CTAs/SM

template <int EPI>
__global__ __launch_bounds__(256, 2)
void gemm_f16_kernel(const __half* __restrict__ A, const __half* __restrict__ B,
                     const float* __restrict__ bias, const float* __restrict__ res,
                     const float* __restrict__ mu, const float* __restrict__ inv,
                     const float* __restrict__ r1, const float* __restrict__ r2,
                     float* __restrict__ outf, __half* __restrict__ outh,
                     int M, int N, int K)
{
    extern __shared__ __align__(1024) unsigned char dsm[];
    const int tid = threadIdx.x;
    const int wid = tid >> 5;
    const int lid = tid & 31;
    const int m0 = blockIdx.y * 128;
    const int n0 = blockIdx.x * 128;
    const uint32_t dsm_b = smem_u32(dsm);

    const int warpM = wid >> 2, warpN = wid & 3;
    const int rl = lid & 15, chh = lid >> 4;

    const __half* At = A + (size_t)m0 * K;
    const __half* Bt = B + (size_t)n0 * K;

    const int nchunk = K >> 6;

    auto load_chunk = [&](int chunk) {
        const uint32_t sb = dsm_b + (chunk % NSTAGEF) * STAGE_BF;
        const int koff = chunk << 6;
        #pragma unroll
        for (int i = 0; i < 8; i++) {
            const int u = i * 256 + tid;           // 0..2047
            const int t = u >> 10;                 // 0=A, 1=B
            const int v = u & 1023;
            const int row = v >> 3, c = v & 7;
            const __half* g = t ? Bt : At;
            const void* gp = g + (size_t)row * K + koff + c * 8;
            const uint32_t sa = sb + t * TILE_B + row * 128 + ((c ^ (row & 7)) << 4);
            cp_async16(sa, gp);
        }
        cp_commit();
    };

    float acc[4][4][4];
    #pragma unroll
    for (int mi = 0; mi < 4; mi++)
        #pragma unroll
        for (int ni = 0; ni < 4; ni++)
            #pragma unroll
            for (int r = 0; r < 4; r++) acc[mi][ni][r] = 0.0f;

    load_chunk(0);
    load_chunk(1);

    for (int c = 0; c < nchunk; c++) {
        if (c < nchunk - 1) cp_wait<1>(); else cp_wait<0>();
        __syncthreads();
        if (c + 2 < nchunk) load_chunk(c + 2);

        const uint32_t st = dsm_b + (c % NSTAGEF) * STAGE_BF;
        #pragma unroll
        for (int ks = 0; ks < 4; ks++) {
            const int kchunk = (ks << 1) | chh;
            uint32_t a[4][4], b[2][4];
            #pragma unroll
            for (int mi = 0; mi < 4; mi++) {
                const int row = warpM * 64 + mi * 16 + rl;
                const uint32_t ad = st + row * 128 + ((kchunk ^ (row & 7)) << 4);
                LDMX4(a[mi][0], a[mi][1], a[mi][2], a[mi][3], ad);
            }
            #pragma unroll
            for (int nj = 0; nj < 2; nj++) {
                const int row = warpN * 32 + nj * 16 + rl;
                const uint32_t bd = st + TILE_B + row * 128 + ((kchunk ^ (row & 7)) << 4);
                LDMX4(b[nj][0], b[nj][1], b[nj][2], b[nj][3], bd);
            }
            #pragma unroll
            for (int mi = 0; mi < 4; mi++)
                #pragma unroll
                for (int ni = 0; ni < 4; ni++) {
                    const int nj = ni >> 1, sel = ni & 1;
                    MMA16816_F16(acc[mi][ni], a[mi], b[nj][sel], b[nj][2 + sel]);
                }
        }
    }

    const int g = lid >> 2, q = lid & 3;
    #pragma unroll
    for (int mi = 0; mi < 4; mi++)
        #pragma unroll
        for (int ni = 0; ni < 4; ni++) {
            const int row = m0 + warpM * 64 + mi * 16 + g;
            const int col = n0 + warpN * 32 + ni * 8 + q * 2;
            const size_t o0 = (size_t)row * N + col;
            const size_t o1 = (size_t)(row + 8) * N + col;
            float v[4];
            if (EPI == 1) {
                // fused LayerNorm affine: inv*acc - inv*mu*r1[n] + r2[n] + bias[n]
                const float2 rr1 = *(const float2*)(r1 + col);
                const float2 rr2 = *(const float2*)(r2 + col);
                const float2 bb  = *(const float2*)(bias + col);
                const float i0 = inv[row],     m0v = mu[row];
                const float i1 = inv[row + 8], m1v = mu[row + 8];
                v[0] = i0 * acc[mi][ni][0] - i0 * m0v * rr1.x + rr2.x + bb.x;
                v[1] = i0 * acc[mi][ni][1] - i0 * m0v * rr1.y + rr2.y + bb.y;
                v[2] = i1 * acc[mi][ni][2] - i1 * m1v * rr1.x + rr2.x + bb.x;
                v[3] = i1 * acc[mi][ni][3] - i1 * m1v * rr1.y + rr2.y + bb.y;
                #pragma unroll
                for (int r = 0; r < 4; r++)
                    v[r] = 0.5f * v[r] * (1.0f + erff(v[r] * 0.70710678118654752f));
                *(__half2*)(outh + o0) = __floats2half2_rn(v[0], v[1]);
                *(__half2*)(outh + o1) = __floats2half2_rn(v[2], v[3]);
            } else {
                const float2 bb = *(const float2*)(bias + col);
                v[0] = acc[mi][ni][0] + bb.x;
                v[1] = acc[mi][ni][1] + bb.y;
                v[2] = acc[mi][ni][2] + bb.x;
                v[3] = acc[mi][ni][3] + bb.y;
                if (EPI == 2) {
                    const float2 q0 = *(const float2*)(res + o0);
                    const float2 q1 = *(const float2*)(res + o1);
                    *(float2*)(outf + o0) = make_float2(v[0] + q0.x, v[1] + q0.y);
                    *(float2*)(outf + o1) = make_float2(v[2] + q1.x, v[3] + q1.y);
                } else {
                    *(__half2*)(outh + o0) = __floats2half2_rn(v[0], v[1]);
                    *(__half2*)(outh + o1) = __floats2half2_rn(v[2], v[3]);
                }
            }
        }
}

// ---------------------------------------------------------------------------
// escale: e = exp(log_scale), b0s = b_omega * e
// ---------------------------------------------------------------------------
__global__ __launch_bounds__(256)
void escale_kernel(const float* __restrict__ log_scale, const float* __restrict__ b0,
                   float* __restrict__ e, float* __restrict__ b0s)
{
    const int i = blockIdx.x * blockDim.x + threadIdx.x;
    if (i >= D_DIM) return;
    const float ev = expf(log_scale[i]);
    e[i] = ev;
    b0s[i] = b0[i] * ev;
}

// ---------------------------------------------------------------------------
// Fused operand prep (segments): x->xf | W0*e->w0f | W1*gamma->w1g | W2->w2f
// ---------------------------------------------------------------------------
static constexpr int PREP_B0 = NROWS * D_DIM / 1024;                 // 16384
static constexpr int PREP_B1 = PREP_B0 + D_DIM * D_DIM / 1024;       // +1024
static constexpr int PREP_B2 = PREP_B1 + HD * FD / 1024;             // +8192
static constexpr int PREP_B3 = PREP_B2 + D_DIM * HD / 1024;          // +2048

__global__ __launch_bounds__(256)
void prep_kernel(const float* __restrict__ x, const float* __restrict__ W0,
                 const float* __restrict__ W1, const float* __restrict__ W2,
                 const float* __restrict__ gamma, const float* __restrict__ e,
                 __half* __restrict__ xf, __half* __restrict__ w0f,
                 __half* __restrict__ w1g, __half* __restrict__ w2f)
{
    const int blk = blockIdx.x;
    const int tid = threadIdx.x;
    if (blk < PREP_B0) {
        const size_t i = (size_t)blk * 256 + tid;     // float4 index
        const float4 v = ((const float4*)x)[i];
        __half2* op = (__half2*)xf;
        op[2 * i]     = __floats2half2_rn(v.x, v.y);
        op[2 * i + 1] = __floats2half2_rn(v.z, v.w);
    } else if (blk < PREP_B1) {
        const size_t i = (size_t)(blk - PREP_B0) * 256 + tid;
        const int n = (int)((i * 4) >> 10);           // row (K=1024 fast)
        const float ev = e[n];
        const float4 v = ((const float4*)W0)[i];
        __half2* op = (__half2*)w0f;
        op[2 * i]     = __floats2half2_rn(v.x * ev, v.y * ev);
        op[2 * i + 1] = __floats2half2_rn(v.z * ev, v.w * ev);
    } else if (blk < PREP_B2) {
        const size_t i = (size_t)(blk - PREP_B1) * 256 + tid;
        const int d = (int)((i * 4) & (FD - 1));
        const float4 v = ((const float4*)W1)[i];
        const float4 gg = *(const float4*)(gamma + d);
        __half2* op = (__half2*)w1g;
        op[2 * i]     = __floats2half2_rn(v.x * gg.x, v.y * gg.y);
        op[2 * i + 1] = __floats2half2_rn(v.z * gg.z, v.w * gg.w);
    } else {
        const size_t i = (size_t)(blk - PREP_B2) * 256 + tid;
        const float4 v = ((const float4*)W2)[i];
        __half2* op = (__half2*)w2f;
        op[2 * i]     = __floats2half2_rn(v.x, v.y);
        op[2 * i + 1] = __floats2half2_rn(v.z, v.w);
    }
}

// r1[n] = sum_d gamma[d]*W1[n,d];  r2[n] = sum_d beta[d]*W1[n,d]. One warp per n.
__global__ __launch_bounds__(256)
void r12_kernel(const float* __restrict__ W1, const float* __restrict__ gamma,
                const float* __restrict__ beta, float* __restrict__ r1,
                float* __restrict__ r2)
{
    const int n = blockIdx.x * 8 + threadIdx.y;
    const int lane = threadIdx.x;
    const float* wr = W1 + (size_t)n * FD;
    float a = 0.0f, b = 0.0f;
    for (int d = lane * 4; d < FD; d += 128) {
        const float4 w = *(const float4*)(wr + d);
        const float4 gg = *(const float4*)(gamma + d);
        const float4 be = *(const float4*)(beta + d);
        a += w.x * gg.x + w.y * gg.y + w.z * gg.z + w.w * gg.w;
        b += w.x * be.x + w.y * be.y + w.z * be.z + w.w * be.w;
    }
    #pragma unroll
    for (int off = 16; off > 0; off >>= 1) {
        a += __shfl_down_sync(0xffffffffu, a, off);
        b += __shfl_down_sync(0xffffffffu, b, off);
    }
    if (lane == 0) { r1[n] = a; r2[n] = b; }
}

// finalize per-row LN stats from 32 deterministic partials
__global__ __launch_bounds__(256)
void rowstat_kernel(const float* __restrict__ rs, const float* __restrict__ rs2,
                    float* __restrict__ mu, float* __restrict__ inv)
{
    const int r = blockIdx.x * blockDim.x + threadIdx.x;
    if (r >= NROWS) return;
    float s1 = 0.0f, s2 = 0.0f;
    #pragma unroll
    for (int j = 0; j < NDBLK; j++) {
        s1 += rs [(size_t)j * NROWS + r];
        s2 += rs2[(size_t)j * NROWS + r];
    }
    const float m = s1 * (1.0f / FD);
    mu[r]  = m;
    inv[r] = rsqrtf(s2 * (1.0f / FD) - m * m + 1e-5f);
}

// ---------------------------------------------------------------------------
// Fused sequential scans -> raw ctx fp16 + deterministic per-row partial sums.
// sincosf -> __sinf/__cosf (phi std ~0.3 rad; MUFU approx error ~2^-21 there,
// negligible vs 2.6e-4 budget). Divides -> __fdividef (MUFU.RCP path).
// ---------------------------------------------------------------------------
__global__ __launch_bounds__(1024)
void scan_kernel(const __half* __restrict__ xf, const __half* __restrict__ omega,
                 __half* __restrict__ ctx,
                 float* __restrict__ rs, float* __restrict__ rs2)
{
    __shared__ float xs[32][33];
    __shared__ float os[32][33];
    __shared__ float ob[4][32][33];

    const int b  = blockIdx.y;
    const int dblk = blockIdx.x;
    const int d0 = dblk * 32;
    const int tx = threadIdx.x;
    const int ty = threadIdx.y;

    const __half* xp = xf    + (size_t)b * S_LEN * D_DIM;
    const __half* op = omega + (size_t)b * S_LEN * D_DIM;
    __half*      cp = ctx   + (size_t)b * S_LEN * FD;
    const int rowbase = b * S_LEN;

    float c0 = 0.0f, c1 = 0.0f, c2 = 0.0f;

    for (int s0 = 0; s0 < S_LEN; s0 += 32) {
        xs[ty][tx] = __half2float(xp[(size_t)(s0 + ty) * D_DIM + d0 + tx]);
        os[ty][tx] = __half2float(op[(size_t)(s0 + ty) * D_DIM + d0 + tx]);
        __syncthreads();

        const float pos = (float)(s0 + tx + 1);
        float w = os[tx][ty] * rsqrtf(pos);

        float pl = w;
        #pragma unroll
        for (int off = 1; off < 32; off <<= 1) {
            float t = __shfl_up_sync(0xffffffffu, pl, off);
            if (tx >= off) pl += t;
        }
        const float phi = c0 + pl;
        c0 += __shfl_sync(0xffffffffu, pl, 31);

        const float sv = __sinf(phi);
        const float cv = __cosf(phi);
        const float xv  = xs[tx][ty];
        const float cmr = xv * cv;
        const float cmi = xv * sv;

        float pr = cmr;
        #pragma unroll
        for (int off = 1; off < 32; off <<= 1) {
            float t = __shfl_up_sync(0xffffffffu, pr, off);
            if (tx >= off) pr += t;
        }
        float pi = cmi;
        #pragma unroll
        for (int off = 1; off < 32; off <<= 1) {
            float t = __shfl_up_sync(0xffffffffu, pi, off);
            if (tx >= off) pi += t;
        }

        const float ip = __fdividef(1.0f, pos);
        const float memr = (c1 + pr) * ip;
        const float memi = (c2 + pi) * ip;
        c1 += __shfl_sync(0xffffffffu, pr, 31);
        c2 += __shfl_sync(0xffffffffu, pi, 31);

        const float retr = memr * cv + memi * sv;
        const float reti = memi * cv - memr * sv;

        ob[0][tx][ty] = cmr;
        ob[1][tx][ty] = cmi;
        ob[2][tx][ty] = retr;
        ob[3][tx][ty] = reti;
        __syncthreads();

        // store phase: thread (tx=d-local=lane, ty=s-local=warp)
        const float v0 = ob[0][ty][tx];
        const float v1 = ob[1][ty][tx];
        const float v2 = ob[2][ty][tx];
        const float v3 = ob[3][ty][tx];
        const size_t ro = (size_t)(s0 + ty) * FD + d0 + tx;
        cp[ro]             = __float2half(v0);
        cp[ro + D_DIM]     = __float2half(v1);
        cp[ro + 2 * D_DIM] = __float2half(v2);
        cp[ro + 3 * D_DIM] = __float2half(v3);

        // deterministic per-row partial sums over this block's 32 channels
        float ls  = v0 + v1 + v2 + v3;
        float ls2 = v0 * v0 + v1 * v1 + v2 * v2 + v3 * v3;
        #pragma unroll
        for (int off = 16; off > 0; off >>= 1) {
            ls  += __shfl_down_sync(0xffffffffu, ls,  off);
            ls2 += __shfl_down_sync(0xffffffffu, ls2, off);
        }
        if (tx == 0) {
            const size_t pidx = (size_t)dblk * NROWS + rowbase + s0 + ty;
            rs [pidx] = ls;
            rs2[pidx] = ls2;
        }
        __syncthreads();
    }
}

// ---------------------------------------------------------------------------
extern "C" void kernel_launch(void* const* d_in, const int* in_sizes, int n_in,
                              void* d_out, int out_size)
{
    const float* x         = (const float*)d_in[0];
    const float* W_omega   = (const float*)d_in[1];
    const float* b_omega   = (const float*)d_in[2];
    const float* log_scale = (const float*)d_in[3];
    const float* ln_gamma  = (const float*)d_in[4];
    const float* ln_beta   = (const float*)d_in[5];
    const float* W1        = (const float*)d_in[6];
    const float* b1        = (const float*)d_in[7];
    const float* W2        = (const float*)d_in[8];
    const float* b2        = (const float*)d_in[9];
    float* out = (float*)d_out;

    __half *xf, *w0f, *omega_p, *cf, *w1g, *w2f, *h1f;
    float *rs, *rs2, *mu, *inv, *r1, *r2, *e, *b0s;
    cudaGetSymbolAddress((void**)&xf,      g_xf);
    cudaGetSymbolAddress((void**)&w0f,     g_w0f);
    cudaGetSymbolAddress((void**)&omega_p, g_omega);
    cudaGetSymbolAddress((void**)&cf,      g_cf);
    cudaGetSymbolAddress((void**)&w1g,     g_w1g);
    cudaGetSymbolAddress((void**)&w2f,     g_w2f);
    cudaGetSymbolAddress((void**)&h1f,     g_h1f);
    cudaGetSymbolAddress((void**)&rs,      g_rs);
    cudaGetSymbolAddress((void**)&rs2,     g_rs2);
    cudaGetSymbolAddress((void**)&mu,      g_mu);
    cudaGetSymbolAddress((void**)&inv,     g_inv);
    cudaGetSymbolAddress((void**)&r1,      g_r1);
    cudaGetSymbolAddress((void**)&r2,      g_r2);
    cudaGetSymbolAddress((void**)&e,       g_e);
    cudaGetSymbolAddress((void**)&b0s,     g_b0s);

    cudaFuncSetAttribute(gemm_f16_kernel<0>, cudaFuncAttributeMaxDynamicSharedMemorySize, GEMM_DSMF);
    cudaFuncSetAttribute(gemm_f16_kernel<1>, cudaFuncAttributeMaxDynamicSharedMemorySize, GEMM_DSMF);
    cudaFuncSetAttribute(gemm_f16_kernel<2>, cudaFuncAttributeMaxDynamicSharedMemorySize, GEMM_DSMF);

    // operand prep
    escale_kernel<<<(D_DIM + 255) / 256, 256>>>(log_scale, b_omega, e, b0s);
    prep_kernel<<<PREP_B3, 256>>>(x, W_omega, W1, W2, ln_gamma, e, xf, w0f, w1g, w2f);
    r12_kernel<<<HD / 8, dim3(32, 8)>>>(W1, ln_gamma, ln_beta, r1, r2);

    // 1) omega*e = x @ (W_omega*e)^T + b_omega*e   (fp16, f16 out)
    gemm_f16_kernel<0><<<dim3(D_DIM / 128, NROWS / 128), 256, GEMM_DSMF>>>(
        xf, w0f, b0s, nullptr, nullptr, nullptr, nullptr, nullptr,
        nullptr, omega_p, NROWS, D_DIM, D_DIM);

    // 2) scans -> raw ctx f16 + LN partial sums
    scan_kernel<<<dim3(NDBLK, B_DIM), dim3(32, 32)>>>(xf, omega_p, cf, rs, rs2);

    // 3) finalize per-row mu, inv
    rowstat_kernel<<<(NROWS + 255) / 256, 256>>>(rs, rs2, mu, inv);

    // 4) h1 = GELU(LN-affine(ctx @ (W1*gamma)^T)) -> f16   (LayerNorm fused)
    gemm_f16_kernel<1><<<dim3(HD / 128, NROWS / 128), 256, GEMM_DSMF>>>(
        cf, w1g, b1, nullptr, mu, inv, r1, r2,
        nullptr, h1f, NROWS, HD, FD);

    // 5) out = x + h1 @ W2^T + b2
    gemm_f16_kernel<2><<<dim3(D_DIM / 128, NROWS / 128), 256, GEMM_DSMF>>>(
        h1f, w2f, b2, x, nullptr, nullptr, nullptr, nullptr,
        out, nullptr, NROWS, D_DIM, HD);
}

// round 12
// speedup vs baseline: 1.0318x; 1.0002x over previous
#include <cuda_runtime.h>
#include <cuda_fp16.h>
#include <math.h>
#include <stdint.h>

// Shapes fixed: B=4, S=4096, D=1024
static constexpr int S_LEN = 4096;
static constexpr int D_DIM = 1024;
static constexpr int B_DIM = 4;
static constexpr int FD    = 4 * D_DIM;     // 4096
static constexpr int HD    = 2 * D_DIM;     // 2048
static constexpr int NROWS = B_DIM * S_LEN; // 16384
static constexpr int NDBLK = D_DIM / 32;    // 32 scan d-blocks

// ---------------- scratch (device globals; no allocs allowed) ----------------
__device__ __half g_xf  [(size_t)NROWS * D_DIM];   // 32 MB  x fp16
__device__ __half g_w0f [(size_t)D_DIM * D_DIM];   //  2 MB  W_omega*e fp16
__device__ __half g_omega[(size_t)NROWS * D_DIM];  // 32 MB  omega*e fp16
__device__ __half g_cf  [(size_t)NROWS * FD];      // 128 MB raw ctx fp16
__device__ __half g_w1g [(size_t)HD * FD];         // 16 MB  W1*gamma fp16
__device__ __half g_w2f [(size_t)D_DIM * HD];      //  4 MB  W2 fp16
__device__ __half g_h1f [(size_t)NROWS * HD];      // 64 MB  GELU output fp16
__device__ float  g_rs  [(size_t)NDBLK * NROWS];   //  2 MB  partial row sums
__device__ float  g_rs2 [(size_t)NDBLK * NROWS];   //  2 MB  partial row sumsq
__device__ float  g_mu  [NROWS];
__device__ float  g_inv [NROWS];
__device__ float  g_r1  [HD];                      // sum_d gamma*W1
__device__ float  g_r2  [HD];                      // sum_d beta*W1
__device__ float  g_e   [D_DIM];                   // exp(log_scale)
__device__ float  g_b0s [D_DIM];                   // b_omega * e

// ---------------- PTX helpers (stable ISA only) ----------------
__device__ __forceinline__ uint32_t smem_u32(const void* p) {
    uint32_t a;
    asm("{ .reg .u64 t; cvta.to.shared.u64 t, %1; cvt.u32.u64 %0, t; }" : "=r"(a) : "l"(p));
    return a;
}
__device__ __forceinline__ void cp_async16(uint32_t saddr, const void* gptr) {
    asm volatile("cp.async.cg.shared.global [%0], [%1], 16;" :: "r"(saddr), "l"(gptr));
}
__device__ __forceinline__ void cp_commit() { asm volatile("cp.async.commit_group;" ::: "memory"); }
template <int N> __device__ __forceinline__ void cp_wait() {
    asm volatile("cp.async.wait_group %0;" :: "n"(N) : "memory");
}

#define LDMX4(r0, r1, r2, r3, addr)                                              \
    asm volatile("ldmatrix.sync.aligned.m8n8.x4.shared.b16 {%0,%1,%2,%3}, [%4];" \
        : "=r"(r0), "=r"(r1), "=r"(r2), "=r"(r3) : "r"(addr))

#define MMA16816_F16(d, a, b0, b1)                                               \
    asm volatile("mma.sync.aligned.m16n8k16.row.col.f32.f16.f16.f32 "            \
        "{%0,%1,%2,%3}, {%4,%5,%6,%7}, {%8,%9}, {%0,%1,%2,%3};"                  \
        : "+f"((d)[0]), "+f"((d)[1]), "+f"((d)[2]), "+f"((d)[3])                 \
        : "r"((a)[0]), "r"((a)[1]), "r"((a)[2]), "r"((a)[3]), "r"(b0), "r"(b1))

// ===========================================================================
// fp16 GEMM (f32 accum): C[M,N] = A[M,K]*B[N,K]^T.  (R8/R11 best config)
// 128x128 tile, BK=64, 3-stage cp.async, 256 thr (8 warps 2x4), warp 64x32.
// EPI 0: + bias           -> f16 out            (GEMM1: omega)
// EPI 1: LN-affine + GELU -> f16 out            (GEMM2, fused LayerNorm)
// EPI 2: + bias + res     -> fp32 out           (GEMM3, residual)
// ===========================================================================
static constexpr int TILE_B    = 128 * 128;           // 16 KB f16 128x64 tile
static constexpr int STAGE_BF  = 2 * TILE_B;          // 32 KB
static constexpr int NSTAGEF   = 3;
static constexpr int GEMM_DSMF = NSTAGEF * STAGE_BF;  // 96 KB -> 2 CTAs/SM

template <int EPI>
__global__ __launch_bounds__(256, 2)
void gemm_f16_kernel(const __half* __restrict__ A, const __half* __restrict__ B,
                     const float* __restrict__ bias, const float* __restrict__ res,
                     const float* __restrict__ mu, const float* __restrict__ inv,
                     const float* __restrict__ r1, const float* __restrict__ r2,
                     float* __restrict__ outf, __half* __restrict__ outh,
                     int M, int N, int K)
{
    extern __shared__ __align__(1024) unsigned char dsm[];
    const int tid = threadIdx.x;
    const int wid = tid >> 5;
    const int lid = tid & 31;
    const int m0 = blockIdx.y * 128;
    const int n0 = blockIdx.x * 128;
    const uint32_t dsm_b = smem_u32(dsm);

    const int warpM = wid >> 2, warpN = wid & 3;
    const int rl = lid & 15, chh = lid >> 4;

    const __half* At = A + (size_t)m0 * K;
    const __half* Bt = B + (size_t)n0 * K;

    const int nchunk = K >> 6;

    auto load_chunk = [&](int chunk) {
        const uint32_t sb = dsm_b + (chunk % NSTAGEF) * STAGE_BF;
        const int koff = chunk << 6;
        #pragma unroll
        for (int i = 0; i < 8; i++) {
            const int u = i * 256 + tid;           // 0..2047
            const int t = u >> 10;                 // 0=A, 1=B
            const int v = u & 1023;
            const int row = v >> 3, c = v & 7;
            const __half* g = t ? Bt : At;
            const void* gp = g + (size_t)row * K + koff + c * 8;
            const uint32_t sa = sb + t * TILE_B + row * 128 + ((c ^ (row & 7)) << 4);
            cp_async16(sa, gp);
        }
        cp_commit();
    };

    float acc[4][4][4];
    #pragma unroll
    for (int mi = 0; mi < 4; mi++)
        #pragma unroll
        for (int ni = 0; ni < 4; ni++)
            #pragma unroll
            for (int r = 0; r < 4; r++) acc[mi][ni][r] = 0.0f;

    load_chunk(0);
    load_chunk(1);

    for (int c = 0; c < nchunk; c++) {
        if (c < nchunk - 1) cp_wait<1>(); else cp_wait<0>();
        __syncthreads();
        if (c + 2 < nchunk) load_chunk(c + 2);

        const uint32_t st = dsm_b + (c % NSTAGEF) * STAGE_BF;
        #pragma unroll
        for (int ks = 0; ks < 4; ks++) {
            const int kchunk = (ks << 1) | chh;
            uint32_t a[4][4], b[2][4];
            #pragma unroll
            for (int mi = 0; mi < 4; mi++) {
                const int row = warpM * 64 + mi * 16 + rl;
                const uint32_t ad = st + row * 128 + ((kchunk ^ (row & 7)) << 4);
                LDMX4(a[mi][0], a[mi][1], a[mi][2], a[mi][3], ad);
            }
            #pragma unroll
            for (int nj = 0; nj < 2; nj++) {
                const int row = warpN * 32 + nj * 16 + rl;
                const uint32_t bd = st + TILE_B + row * 128 + ((kchunk ^ (row & 7)) << 4);
                LDMX4(b[nj][0], b[nj][1], b[nj][2], b[nj][3], bd);
            }
            #pragma unroll
            for (int mi = 0; mi < 4; mi++)
                #pragma unroll
                for (int ni = 0; ni < 4; ni++) {
                    const int nj = ni >> 1, sel = ni & 1;
                    MMA16816_F16(acc[mi][ni], a[mi], b[nj][sel], b[nj][2 + sel]);
                }
        }
    }

    const int g = lid >> 2, q = lid & 3;
    #pragma unroll
    for (int mi = 0; mi < 4; mi++)
        #pragma unroll
        for (int ni = 0; ni < 4; ni++) {
            const int row = m0 + warpM * 64 + mi * 16 + g;
            const int col = n0 + warpN * 32 + ni * 8 + q * 2;
            const size_t o0 = (size_t)row * N + col;
            const size_t o1 = (size_t)(row + 8) * N + col;
            float v[4];
            if (EPI == 1) {
                // fused LayerNorm affine: inv*acc - inv*mu*r1[n] + r2[n] + bias[n]
                const float2 rr1 = *(const float2*)(r1 + col);
                const float2 rr2 = *(const float2*)(r2 + col);
                const float2 bb  = *(const float2*)(bias + col);
                const float i0 = inv[row],     m0v = mu[row];
                const float i1 = inv[row + 8], m1v = mu[row + 8];
                v[0] = i0 * acc[mi][ni][0] - i0 * m0v * rr1.x + rr2.x + bb.x;
                v[1] = i0 * acc[mi][ni][1] - i0 * m0v * rr1.y + rr2.y + bb.y;
                v[2] = i1 * acc[mi][ni][2] - i1 * m1v * rr1.x + rr2.x + bb.x;
                v[3] = i1 * acc[mi][ni][3] - i1 * m1v * rr1.y + rr2.y + bb.y;
                #pragma unroll
                for (int r = 0; r < 4; r++)
                    v[r] = 0.5f * v[r] * (1.0f + erff(v[r] * 0.70710678118654752f));
                *(__half2*)(outh + o0) = __floats2half2_rn(v[0], v[1]);
                *(__half2*)(outh + o1) = __floats2half2_rn(v[2], v[3]);
            } else {
                const float2 bb = *(const float2*)(bias + col);
                v[0] = acc[mi][ni][0] + bb.x;
                v[1] = acc[mi][ni][1] + bb.y;
                v[2] = acc[mi][ni][2] + bb.x;
                v[3] = acc[mi][ni][3] + bb.y;
                if (EPI == 2) {
                    const float2 q0 = *(const float2*)(res + o0);
                    const float2 q1 = *(const float2*)(res + o1);
                    *(float2*)(outf + o0) = make_float2(v[0] + q0.x, v[1] + q0.y);
                    *(float2*)(outf + o1) = make_float2(v[2] + q1.x, v[3] + q1.y);
                } else {
                    *(__half2*)(outh + o0) = __floats2half2_rn(v[0], v[1]);
                    *(__half2*)(outh + o1) = __floats2half2_rn(v[2], v[3]);
                }
            }
        }
}

// ---------------------------------------------------------------------------
// escale: e = exp(log_scale), b0s = b_omega * e
// ---------------------------------------------------------------------------
__global__ __launch_bounds__(256)
void escale_kernel(const float* __restrict__ log_scale, const float* __restrict__ b0,
                   float* __restrict__ e, float* __restrict__ b0s)
{
    const int i = blockIdx.x * blockDim.x + threadIdx.x;
    if (i >= D_DIM) return;
    const float ev = expf(log_scale[i]);
    e[i] = ev;
    b0s[i] = b0[i] * ev;
}

// ---------------------------------------------------------------------------
// Fused operand prep (segments): x->xf | W0*e->w0f | W1*gamma->w1g | W2->w2f
// ---------------------------------------------------------------------------
static constexpr int PREP_B0 = NROWS * D_DIM / 1024;                 // 16384
static constexpr int PREP_B1 = PREP_B0 + D_DIM * D_DIM / 1024;       // +1024
static constexpr int PREP_B2 = PREP_B1 + HD * FD / 1024;             // +8192
static constexpr int PREP_B3 = PREP_B2 + D_DIM * HD / 1024;          // +2048

__global__ __launch_bounds__(256)
void prep_kernel(const float* __restrict__ x, const float* __restrict__ W0,
                 const float* __restrict__ W1, const float* __restrict__ W2,
                 const float* __restrict__ gamma, const float* __restrict__ e,
                 __half* __restrict__ xf, __half* __restrict__ w0f,
                 __half* __restrict__ w1g, __half* __restrict__ w2f)
{
    const int blk = blockIdx.x;
    const int tid = threadIdx.x;
    if (blk < PREP_B0) {
        const size_t i = (size_t)blk * 256 + tid;     // float4 index
        const float4 v = ((const float4*)x)[i];
        __half2* op = (__half2*)xf;
        op[2 * i]     = __floats2half2_rn(v.x, v.y);
        op[2 * i + 1] = __floats2half2_rn(v.z, v.w);
    } else if (blk < PREP_B1) {
        const size_t i = (size_t)(blk - PREP_B0) * 256 + tid;
        const int n = (int)((i * 4) >> 10);           // row (K=1024 fast)
        const float ev = e[n];
        const float4 v = ((const float4*)W0)[i];
        __half2* op = (__half2*)w0f;
        op[2 * i]     = __floats2half2_rn(v.x * ev, v.y * ev);
        op[2 * i + 1] = __floats2half2_rn(v.z * ev, v.w * ev);
    } else if (blk < PREP_B2) {
        const size_t i = (size_t)(blk - PREP_B1) * 256 + tid;
        const int d = (int)((i * 4) & (FD - 1));
        const float4 v = ((const float4*)W1)[i];
        const float4 gg = *(const float4*)(gamma + d);
        __half2* op = (__half2*)w1g;
        op[2 * i]     = __floats2half2_rn(v.x * gg.x, v.y * gg.y);
        op[2 * i + 1] = __floats2half2_rn(v.z * gg.z, v.w * gg.w);
    } else {
        const size_t i = (size_t)(blk - PREP_B2) * 256 + tid;
        const float4 v = ((const float4*)W2)[i];
        __half2* op = (__half2*)w2f;
        op[2 * i]     = __floats2half2_rn(v.x, v.y);
        op[2 * i + 1] = __floats2half2_rn(v.z, v.w);
    }
}

// r1[n] = sum_d gamma[d]*W1[n,d];  r2[n] = sum_d beta[d]*W1[n,d]. One warp per n.
__global__ __launch_bounds__(256)
void r12_kernel(const float* __restrict__ W1, const float* __restrict__ gamma,
                const float* __restrict__ beta, float* __restrict__ r1,
                float* __restrict__ r2)
{
    const int n = blockIdx.x * 8 + threadIdx.y;
    const int lane = threadIdx.x;
    const float* wr = W1 + (size_t)n * FD;
    float a = 0.0f, b = 0.0f;
    for (int d = lane * 4; d < FD; d += 128) {
        const float4 w = *(const float4*)(wr + d);
        const float4 gg = *(const float4*)(gamma + d);
        const float4 be = *(const float4*)(beta + d);
        a += w.x * gg.x + w.y * gg.y + w.z * gg.z + w.w * gg.w;
        b += w.x * be.x + w.y * be.y + w.z * be.z + w.w * be.w;
    }
    #pragma unroll
    for (int off = 16; off > 0; off >>= 1) {
        a += __shfl_down_sync(0xffffffffu, a, off);
        b += __shfl_down_sync(0xffffffffu, b, off);
    }
    if (lane == 0) { r1[n] = a; r2[n] = b; }
}

// finalize per-row LN stats from 32 deterministic partials
__global__ __launch_bounds__(256)
void rowstat_kernel(const float* __restrict__ rs, const float* __restrict__ rs2,
                    float* __restrict__ mu, float* __restrict__ inv)
{
    const int r = blockIdx.x * blockDim.x + threadIdx.x;
    if (r >= NROWS) return;
    float s1 = 0.0f, s2 = 0.0f;
    #pragma unroll
    for (int j = 0; j < NDBLK; j++) {
        s1 += rs [(size_t)j * NROWS + r];
        s2 += rs2[(size_t)j * NROWS + r];
    }
    const float m = s1 * (1.0f / FD);
    mu[r]  = m;
    inv[r] = rsqrtf(s2 * (1.0f / FD) - m * m + 1e-5f);
}

// ---------------------------------------------------------------------------
// Fused sequential scans -> raw ctx fp16 + deterministic per-row partial sums.
// Register-prefetched tiles: next tile's LDGs are issued right after the
// producer barrier so their ~600-cyc latency overlaps the current tile's
// scan compute + ctx stores (previously fully exposed per iteration).
// ---------------------------------------------------------------------------
__global__ __launch_bounds__(1024)
void scan_kernel(const __half* __restrict__ xf, const __half* __restrict__ omega,
                 __half* __restrict__ ctx,
                 float* __restrict__ rs, float* __restrict__ rs2)
{
    __shared__ float xs[32][33];
    __shared__ float os[32][33];
    __shared__ float ob[4][32][33];

    const int b  = blockIdx.y;
    const int dblk = blockIdx.x;
    const int d0 = dblk * 32;
    const int tx = threadIdx.x;
    const int ty = threadIdx.y;

    const __half* xp = xf    + (size_t)b * S_LEN * D_DIM;
    const __half* op = omega + (size_t)b * S_LEN * D_DIM;
    __half*      cp = ctx   + (size_t)b * S_LEN * FD;
    const int rowbase = b * S_LEN;

    float c0 = 0.0f, c1 = 0.0f, c2 = 0.0f;

    // prefetch tile 0
    float xreg = __half2float(xp[(size_t)ty * D_DIM + d0 + tx]);
    float oreg = __half2float(op[(size_t)ty * D_DIM + d0 + tx]);

    for (int s0 = 0; s0 < S_LEN; s0 += 32) {
        // publish prefetched tile
        xs[ty][tx] = xreg;
        os[ty][tx] = oreg;
        __syncthreads();

        // issue next tile's loads early (latency hidden behind compute below)
        if (s0 + 32 < S_LEN) {
            const size_t nb = (size_t)(s0 + 32 + ty) * D_DIM + d0 + tx;
            xreg = __half2float(xp[nb]);
            oreg = __half2float(op[nb]);
        }

        // scan phase: lane=tx is s-local, warp=ty is d-local
        const float pos = (float)(s0 + tx + 1);
        float w = os[tx][ty] * rsqrtf(pos);

        float pl = w;
        #pragma unroll
        for (int off = 1; off < 32; off <<= 1) {
            float t = __shfl_up_sync(0xffffffffu, pl, off);
            if (tx >= off) pl += t;
        }
        const float phi = c0 + pl;
        c0 += __shfl_sync(0xffffffffu, pl, 31);

        const float sv = __sinf(phi);
        const float cv = __cosf(phi);
        const float xv  = xs[tx][ty];
        const float cmr = xv * cv;
        const float cmi = xv * sv;

        float pr = cmr;
        #pragma unroll
        for (int off = 1; off < 32; off <<= 1) {
            float t = __shfl_up_sync(0xffffffffu, pr, off);
            if (tx >= off) pr += t;
        }
        float pi = cmi;
        #pragma unroll
        for (int off = 1; off < 32; off <<= 1) {
            float t = __shfl_up_sync(0xffffffffu, pi, off);
            if (tx >= off) pi += t;
        }

        const float ip = __fdividef(1.0f, pos);
        const float memr = (c1 + pr) * ip;
        const float memi = (c2 + pi) * ip;
        c1 += __shfl_sync(0xffffffffu, pr, 31);
        c2 += __shfl_sync(0xffffffffu, pi, 31);

        const float retr = memr * cv + memi * sv;
        const float reti = memi * cv - memr * sv;

        ob[0][tx][ty] = cmr;
        ob[1][tx][ty] = cmi;
        ob[2][tx][ty] = retr;
        ob[3][tx][ty] = reti;
        __syncthreads();

        // store phase: thread (tx=d-local=lane, ty=s-local=warp)
        const float v0 = ob[0][ty][tx];
        const float v1 = ob[1][ty][tx];
        const float v2 = ob[2][ty][tx];
        const float v3 = ob[3][ty][tx];
        const size_t ro = (size_t)(s0 + ty) * FD + d0 + tx;
        cp[ro]             = __float2half(v0);
        cp[ro + D_DIM]     = __float2half(v1);
        cp[ro + 2 * D_DIM] = __float2half(v2);
        cp[ro + 3 * D_DIM] = __float2half(v3);

        // deterministic per-row partial sums over this block's 32 channels
        float ls  = v0 + v1 + v2 + v3;
        float ls2 = v0 * v0 + v1 * v1 + v2 * v2 + v3 * v3;
        #pragma unroll
        for (int off = 16; off > 0; off >>= 1) {
            ls  += __shfl_down_sync(0xffffffffu, ls,  off);
            ls2 += __shfl_down_sync(0xffffffffu, ls2, off);
        }
        if (tx == 0) {
            const size_t pidx = (size_t)dblk * NROWS + rowbase + s0 + ty;
            rs [pidx] = ls;
            rs2[pidx] = ls2;
        }
        // NOTE: no trailing barrier needed — next iteration's xs/os writes are
        // ordered after this iteration's compute reads by the ob barrier above,
        // and ob reads here complete before the next ob writes (guarded by the
        // next iteration's first barrier).
    }
}

// ---------------------------------------------------------------------------
extern "C" void kernel_launch(void* const* d_in, const int* in_sizes, int n_in,
                              void* d_out, int out_size)
{
    const float* x         = (const float*)d_in[0];
    const float* W_omega   = (const float*)d_in[1];
    const float* b_omega   = (const float*)d_in[2];
    const float* log_scale = (const float*)d_in[3];
    const float* ln_gamma  = (const float*)d_in[4];
    const float* ln_beta   = (const float*)d_in[5];
    const float* W1        = (const float*)d_in[6];
    const float* b1        = (const float*)d_in[7];
    const float* W2        = (const float*)d_in[8];
    const float* b2        = (const float*)d_in[9];
    float* out = (float*)d_out;

    __half *xf, *w0f, *omega_p, *cf, *w1g, *w2f, *h1f;
    float *rs, *rs2, *mu, *inv, *r1, *r2, *e, *b0s;
    cudaGetSymbolAddress((void**)&xf,      g_xf);
    cudaGetSymbolAddress((void**)&w0f,     g_w0f);
    cudaGetSymbolAddress((void**)&omega_p, g_omega);
    cudaGetSymbolAddress((void**)&cf,      g_cf);
    cudaGetSymbolAddress((void**)&w1g,     g_w1g);
    cudaGetSymbolAddress((void**)&w2f,     g_w2f);
    cudaGetSymbolAddress((void**)&h1f,     g_h1f);
    cudaGetSymbolAddress((void**)&rs,      g_rs);
    cudaGetSymbolAddress((void**)&rs2,     g_rs2);
    cudaGetSymbolAddress((void**)&mu,      g_mu);
    cudaGetSymbolAddress((void**)&inv,     g_inv);
    cudaGetSymbolAddress((void**)&r1,      g_r1);
    cudaGetSymbolAddress((void**)&r2,      g_r2);
    cudaGetSymbolAddress((void**)&e,       g_e);
    cudaGetSymbolAddress((void**)&b0s,     g_b0s);

    cudaFuncSetAttribute(gemm_f16_kernel<0>, cudaFuncAttributeMaxDynamicSharedMemorySize, GEMM_DSMF);
    cudaFuncSetAttribute(gemm_f16_kernel<1>, cudaFuncAttributeMaxDynamicSharedMemorySize, GEMM_DSMF);
    cudaFuncSetAttribute(gemm_f16_kernel<2>, cudaFuncAttributeMaxDynamicSharedMemorySize, GEMM_DSMF);

    // operand prep
    escale_kernel<<<(D_DIM + 255) / 256, 256>>>(log_scale, b_omega, e, b0s);
    prep_kernel<<<PREP_B3, 256>>>(x, W_omega, W1, W2, ln_gamma, e, xf, w0f, w1g, w2f);
    r12_kernel<<<HD / 8, dim3(32, 8)>>>(W1, ln_gamma, ln_beta, r1, r2);

    // 1) omega*e = x @ (W_omega*e)^T + b_omega*e   (fp16, f16 out)
    gemm_f16_kernel<0><<<dim3(D_DIM / 128, NROWS / 128), 256, GEMM_DSMF>>>(
        xf, w0f, b0s, nullptr, nullptr, nullptr, nullptr, nullptr,
        nullptr, omega_p, NROWS, D_DIM, D_DIM);

    // 2) scans -> raw ctx f16 + LN partial sums
    scan_kernel<<<dim3(NDBLK, B_DIM), dim3(32, 32)>>>(xf, omega_p, cf, rs, rs2);

    // 3) finalize per-row mu, inv
    rowstat_kernel<<<(NROWS + 255) / 256, 256>>>(rs, rs2, mu, inv);

    // 4) h1 = GELU(LN-affine(ctx @ (W1*gamma)^T)) -> f16   (LayerNorm fused)
    gemm_f16_kernel<1><<<dim3(HD / 128, NROWS / 128), 256, GEMM_DSMF>>>(
        cf, w1g, b1, nullptr, mu, inv, r1, r2,
        nullptr, h1f, NROWS, HD, FD);

    // 5) out = x + h1 @ W2^T + b2
    gemm_f16_kernel<2><<<dim3(D_DIM / 128, NROWS / 128), 256, GEMM_DSMF>>>(
        h1f, w2f, b2, x, nullptr, nullptr, nullptr, nullptr,
        out, nullptr, NROWS, D_DIM, HD);
}

// round 13
// speedup vs baseline: 1.0702x; 1.0372x over previous
#include <cuda_runtime.h>
#include <cuda_fp16.h>
#include <math.h>
#include <stdint.h>

// Shapes fixed: B=4, S=4096, D=1024
static constexpr int S_LEN = 4096;
static constexpr int D_DIM = 1024;
static constexpr int B_DIM = 4;
static constexpr int FD    = 4 * D_DIM;     // 4096
static constexpr int HD    = 2 * D_DIM;     // 2048
static constexpr int NROWS = B_DIM * S_LEN; // 16384
static constexpr int NDBLK = D_DIM / 32;    // 32 scan d-blocks

// ---------------- scratch (device globals; no allocs allowed) ----------------
__device__ __half g_xf  [(size_t)NROWS * D_DIM];   // 32 MB  x fp16
__device__ __half g_w0f [(size_t)D_DIM * D_DIM];   //  2 MB  W_omega*e fp16
__device__ __half g_omega[(size_t)NROWS * D_DIM];  // 32 MB  omega*e fp16
__device__ __half g_cf  [(size_t)NROWS * FD];      // 128 MB raw ctx fp16
__device__ __half g_w1g [(size_t)HD * FD];         // 16 MB  W1*gamma fp16
__device__ __half g_w2f [(size_t)D_DIM * HD];      //  4 MB  W2 fp16
__device__ __half g_h1f [(size_t)NROWS * HD];      // 64 MB  GELU output fp16
__device__ float  g_rs  [(size_t)NDBLK * NROWS];   //  2 MB  partial row sums
__device__ float  g_rs2 [(size_t)NDBLK * NROWS];   //  2 MB  partial row sumsq
__device__ float  g_mu  [NROWS];
__device__ float  g_inv [NROWS];
__device__ float  g_r1  [HD];                      // sum_d gamma*W1
__device__ float  g_r2  [HD];                      // sum_d beta*W1
__device__ float  g_e   [D_DIM];                   // exp(log_scale)
__device__ float  g_b0s [D_DIM];                   // b_omega * e

// ---------------- PTX helpers (stable ISA only) ----------------
__device__ __forceinline__ uint32_t smem_u32(const void* p) {
    uint32_t a;
    asm("{ .reg .u64 t; cvta.to.shared.u64 t, %1; cvt.u32.u64 %0, t; }" : "=r"(a) : "l"(p));
    return a;
}
__device__ __forceinline__ void cp_async16(uint32_t saddr, const void* gptr) {
    asm volatile("cp.async.cg.shared.global [%0], [%1], 16;" :: "r"(saddr), "l"(gptr));
}
__device__ __forceinline__ void cp_commit() { asm volatile("cp.async.commit_group;" ::: "memory"); }
template <int N> __device__ __forceinline__ void cp_wait() {
    asm volatile("cp.async.wait_group %0;" :: "n"(N) : "memory");
}

#define LDMX4(r0, r1, r2, r3, addr)                                              \
    asm volatile("ldmatrix.sync.aligned.m8n8.x4.shared.b16 {%0,%1,%2,%3}, [%4];" \
        : "=r"(r0), "=r"(r1), "=r"(r2), "=r"(r3) : "r"(addr))

#define MMA16816_F16(d, a, b0, b1)                                               \
    asm volatile("mma.sync.aligned.m16n8k16.row.col.f32.f16.f16.f32 "            \
        "{%0,%1,%2,%3}, {%4,%5,%6,%7}, {%8,%9}, {%0,%1,%2,%3};"                  \
        : "+f"((d)[0]), "+f"((d)[1]), "+f"((d)[2]), "+f"((d)[3])                 \
        : "r"((a)[0]), "r"((a)[1]), "r"((a)[2]), "r"((a)[3]), "r"(b0), "r"(b1))

// ===========================================================================
// fp16 GEMM (f32 accum): C[M,N] = A[M,K]*B[N,K]^T.  (best-measured config)
// 128x128 tile, BK=64, 3-stage cp.async, 256 thr (8 warps 2x4), warp 64x32.
// At the f32-acc HMMA roof (rt=16/SMSP): tensor=54% of ncu-normalized peak.
// EPI 0: + bias           -> f16 out            (GEMM1: omega)
// EPI 1: LN-affine + GELU -> f16 out            (GEMM2, fused LayerNorm)
// EPI 2: + bias + res     -> fp32 out           (GEMM3, residual)
// ===========================================================================
static constexpr int TILE_B    = 128 * 128;           // 16 KB f16 128x64 tile
static constexpr int STAGE_BF  = 2 * TILE_B;          // 32 KB
static constexpr int NSTAGEF   = 3;
static constexpr int GEMM_DSMF = NSTAGEF * STAGE_BF;  // 96 KB -> 2 CTAs/SM

template <int EPI>
__global__ __launch_bounds__(256, 2)
void gemm_f16_kernel(const __half* __restrict__ A, const __half* __restrict__ B,
                     const float* __restrict__ bias, const float* __restrict__ res,
                     const float* __restrict__ mu, const float* __restrict__ inv,
                     const float* __restrict__ r1, const float* __restrict__ r2,
                     float* __restrict__ outf, __half* __restrict__ outh,
                     int M, int N, int K)
{
    extern __shared__ __align__(1024) unsigned char dsm[];
    const int tid = threadIdx.x;
    const int wid = tid >> 5;
    const int lid = tid & 31;
    const int m0 = blockIdx.y * 128;
    const int n0 = blockIdx.x * 128;
    const uint32_t dsm_b = smem_u32(dsm);

    const int warpM = wid >> 2, warpN = wid & 3;
    const int rl = lid & 15, chh = lid >> 4;

    const __half* At = A + (size_t)m0 * K;
    const __half* Bt = B + (size_t)n0 * K;

    const int nchunk = K >> 6;

    auto load_chunk = [&](int chunk) {
        const uint32_t sb = dsm_b + (chunk % NSTAGEF) * STAGE_BF;
        const int koff = chunk << 6;
        #pragma unroll
        for (int i = 0; i < 8; i++) {
            const int u = i * 256 + tid;           // 0..2047
            const int t = u >> 10;                 // 0=A, 1=B
            const int v = u & 1023;
            const int row = v >> 3, c = v & 7;
            const __half* g = t ? Bt : At;
            const void* gp = g + (size_t)row * K + koff + c * 8;
            const uint32_t sa = sb + t * TILE_B + row * 128 + ((c ^ (row & 7)) << 4);
            cp_async16(sa, gp);
        }
        cp_commit();
    };

    float acc[4][4][4];
    #pragma unroll
    for (int mi = 0; mi < 4; mi++)
        #pragma unroll
        for (int ni = 0; ni < 4; ni++)
            #pragma unroll
            for (int r = 0; r < 4; r++) acc[mi][ni][r] = 0.0f;

    load_chunk(0);
    load_chunk(1);

    for (int c = 0; c < nchunk; c++) {
        if (c < nchunk - 1) cp_wait<1>(); else cp_wait<0>();
        __syncthreads();
        if (c + 2 < nchunk) load_chunk(c + 2);

        const uint32_t st = dsm_b + (c % NSTAGEF) * STAGE_BF;
        #pragma unroll
        for (int ks = 0; ks < 4; ks++) {
            const int kchunk = (ks << 1) | chh;
            uint32_t a[4][4], b[2][4];
            #pragma unroll
            for (int mi = 0; mi < 4; mi++) {
                const int row = warpM * 64 + mi * 16 + rl;
                const uint32_t ad = st + row * 128 + ((kchunk ^ (row & 7)) << 4);
                LDMX4(a[mi][0], a[mi][1], a[mi][2], a[mi][3], ad);
            }
            #pragma unroll
            for (int nj = 0; nj < 2; nj++) {
                const int row = warpN * 32 + nj * 16 + rl;
                const uint32_t bd = st + TILE_B + row * 128 + ((kchunk ^ (row & 7)) << 4);
                LDMX4(b[nj][0], b[nj][1], b[nj][2], b[nj][3], bd);
            }
            #pragma unroll
            for (int mi = 0; mi < 4; mi++)
                #pragma unroll
                for (int ni = 0; ni < 4; ni++) {
                    const int nj = ni >> 1, sel = ni & 1;
                    MMA16816_F16(acc[mi][ni], a[mi], b[nj][sel], b[nj][2 + sel]);
                }
        }
    }

    const int g = lid >> 2, q = lid & 3;
    #pragma unroll
    for (int mi = 0; mi < 4; mi++)
        #pragma unroll
        for (int ni = 0; ni < 4; ni++) {
            const int row = m0 + warpM * 64 + mi * 16 + g;
            const int col = n0 + warpN * 32 + ni * 8 + q * 2;
            const size_t o0 = (size_t)row * N + col;
            const size_t o1 = (size_t)(row + 8) * N + col;
            float v[4];
            if (EPI == 1) {
                // fused LayerNorm affine: inv*acc - inv*mu*r1[n] + r2[n] + bias[n]
                const float2 rr1 = *(const float2*)(r1 + col);
                const float2 rr2 = *(const float2*)(r2 + col);
                const float2 bb  = *(const float2*)(bias + col);
                const float i0 = inv[row],     m0v = mu[row];
                const float i1 = inv[row + 8], m1v = mu[row + 8];
                v[0] = i0 * acc[mi][ni][0] - i0 * m0v * rr1.x + rr2.x + bb.x;
                v[1] = i0 * acc[mi][ni][1] - i0 * m0v * rr1.y + rr2.y + bb.y;
                v[2] = i1 * acc[mi][ni][2] - i1 * m1v * rr1.x + rr2.x + bb.x;
                v[3] = i1 * acc[mi][ni][3] - i1 * m1v * rr1.y + rr2.y + bb.y;
                #pragma unroll
                for (int r = 0; r < 4; r++)
                    v[r] = 0.5f * v[r] * (1.0f + erff(v[r] * 0.70710678118654752f));
                *(__half2*)(outh + o0) = __floats2half2_rn(v[0], v[1]);
                *(__half2*)(outh + o1) = __floats2half2_rn(v[2], v[3]);
            } else {
                const float2 bb = *(const float2*)(bias + col);
                v[0] = acc[mi][ni][0] + bb.x;
                v[1] = acc[mi][ni][1] + bb.y;
                v[2] = acc[mi][ni][2] + bb.x;
                v[3] = acc[mi][ni][3] + bb.y;
                if (EPI == 2) {
                    const float2 q0 = *(const float2*)(res + o0);
                    const float2 q1 = *(const float2*)(res + o1);
                    *(float2*)(outf + o0) = make_float2(v[0] + q0.x, v[1] + q0.y);
                    *(float2*)(outf + o1) = make_float2(v[2] + q1.x, v[3] + q1.y);
                } else {
                    *(__half2*)(outh + o0) = __floats2half2_rn(v[0], v[1]);
                    *(__half2*)(outh + o1) = __floats2half2_rn(v[2], v[3]);
                }
            }
        }
}

// ---------------------------------------------------------------------------
// escale: e = exp(log_scale), b0s = b_omega * e
// ---------------------------------------------------------------------------
__global__ __launch_bounds__(256)
void escale_kernel(const float* __restrict__ log_scale, const float* __restrict__ b0,
                   float* __restrict__ e, float* __restrict__ b0s)
{
    const int i = blockIdx.x * blockDim.x + threadIdx.x;
    if (i >= D_DIM) return;
    const float ev = expf(log_scale[i]);
    e[i] = ev;
    b0s[i] = b0[i] * ev;
}

// ---------------------------------------------------------------------------
// Fused operand prep (segments): x->xf | W0*e->w0f | W1*gamma->w1g | W2->w2f
// ---------------------------------------------------------------------------
static constexpr int PREP_B0 = NROWS * D_DIM / 1024;                 // 16384
static constexpr int PREP_B1 = PREP_B0 + D_DIM * D_DIM / 1024;       // +1024
static constexpr int PREP_B2 = PREP_B1 + HD * FD / 1024;             // +8192
static constexpr int PREP_B3 = PREP_B2 + D_DIM * HD / 1024;          // +2048

__global__ __launch_bounds__(256)
void prep_kernel(const float* __restrict__ x, const float* __restrict__ W0,
                 const float* __restrict__ W1, const float* __restrict__ W2,
                 const float* __restrict__ gamma, const float* __restrict__ e,
                 __half* __restrict__ xf, __half* __restrict__ w0f,
                 __half* __restrict__ w1g, __half* __restrict__ w2f)
{
    const int blk = blockIdx.x;
    const int tid = threadIdx.x;
    if (blk < PREP_B0) {
        const size_t i = (size_t)blk * 256 + tid;     // float4 index
        const float4 v = ((const float4*)x)[i];
        __half2* op = (__half2*)xf;
        op[2 * i]     = __floats2half2_rn(v.x, v.y);
        op[2 * i + 1] = __floats2half2_rn(v.z, v.w);
    } else if (blk < PREP_B1) {
        const size_t i = (size_t)(blk - PREP_B0) * 256 + tid;
        const int n = (int)((i * 4) >> 10);           // row (K=1024 fast)
        const float ev = e[n];
        const float4 v = ((const float4*)W0)[i];
        __half2* op = (__half2*)w0f;
        op[2 * i]     = __floats2half2_rn(v.x * ev, v.y * ev);
        op[2 * i + 1] = __floats2half2_rn(v.z * ev, v.w * ev);
    } else if (blk < PREP_B2) {
        const size_t i = (size_t)(blk - PREP_B1) * 256 + tid;
        const int d = (int)((i * 4) & (FD - 1));
        const float4 v = ((const float4*)W1)[i];
        const float4 gg = *(const float4*)(gamma + d);
        __half2* op = (__half2*)w1g;
        op[2 * i]     = __floats2half2_rn(v.x * gg.x, v.y * gg.y);
        op[2 * i + 1] = __floats2half2_rn(v.z * gg.z, v.w * gg.w);
    } else {
        const size_t i = (size_t)(blk - PREP_B2) * 256 + tid;
        const float4 v = ((const float4*)W2)[i];
        __half2* op = (__half2*)w2f;
        op[2 * i]     = __floats2half2_rn(v.x, v.y);
        op[2 * i + 1] = __floats2half2_rn(v.z, v.w);
    }
}

// r1[n] = sum_d gamma[d]*W1[n,d];  r2[n] = sum_d beta[d]*W1[n,d]. One warp per n.
__global__ __launch_bounds__(256)
void r12_kernel(const float* __restrict__ W1, const float* __restrict__ gamma,
                const float* __restrict__ beta, float* __restrict__ r1,
                float* __restrict__ r2)
{
    const int n = blockIdx.x * 8 + threadIdx.y;
    const int lane = threadIdx.x;
    const float* wr = W1 + (size_t)n * FD;
    float a = 0.0f, b = 0.0f;
    for (int d = lane * 4; d < FD; d += 128) {
        const float4 w = *(const float4*)(wr + d);
        const float4 gg = *(const float4*)(gamma + d);
        const float4 be = *(const float4*)(beta + d);
        a += w.x * gg.x + w.y * gg.y + w.z * gg.z + w.w * gg.w;
        b += w.x * be.x + w.y * be.y + w.z * be.z + w.w * be.w;
    }
    #pragma unroll
    for (int off = 16; off > 0; off >>= 1) {
        a += __shfl_down_sync(0xffffffffu, a, off);
        b += __shfl_down_sync(0xffffffffu, b, off);
    }
    if (lane == 0) { r1[n] = a; r2[n] = b; }
}

// finalize per-row LN stats from 32 deterministic partials
__global__ __launch_bounds__(256)
void rowstat_kernel(const float* __restrict__ rs, const float* __restrict__ rs2,
                    float* __restrict__ mu, float* __restrict__ inv)
{
    const int r = blockIdx.x * blockDim.x + threadIdx.x;
    if (r >= NROWS) return;
    float s1 = 0.0f, s2 = 0.0f;
    #pragma unroll
    for (int j = 0; j < NDBLK; j++) {
        s1 += rs [(size_t)j * NROWS + r];
        s2 += rs2[(size_t)j * NROWS + r];
    }
    const float m = s1 * (1.0f / FD);
    mu[r]  = m;
    inv[r] = rsqrtf(s2 * (1.0f / FD) - m * m + 1e-5f);
}

// ---------------------------------------------------------------------------
// Fused sequential scans -> raw ctx fp16 + deterministic per-row partial sums.
// STILE=64: two chained 32-lane warp scans per iteration (carries forwarded in
// registers, bitwise-identical order) -> 64 iterations instead of 128, half
// the barriers and loop overhead on the serial critical path.
// ---------------------------------------------------------------------------
__global__ __launch_bounds__(1024)
void scan_kernel(const __half* __restrict__ xf, const __half* __restrict__ omega,
                 __half* __restrict__ ctx,
                 float* __restrict__ rs, float* __restrict__ rs2)
{
    __shared__ float xs[64][33];
    __shared__ float os[64][33];
    __shared__ float ob[4][64][33];

    const int b  = blockIdx.y;
    const int dblk = blockIdx.x;
    const int d0 = dblk * 32;
    const int tx = threadIdx.x;
    const int ty = threadIdx.y;

    const __half* xp = xf    + (size_t)b * S_LEN * D_DIM;
    const __half* op = omega + (size_t)b * S_LEN * D_DIM;
    __half*      cp = ctx   + (size_t)b * S_LEN * FD;
    const int rowbase = b * S_LEN;

    float c0 = 0.0f, c1 = 0.0f, c2 = 0.0f;

    // prefetch tile 0 (rows ty and ty+32)
    float xr0 = __half2float(xp[(size_t)ty * D_DIM + d0 + tx]);
    float or0 = __half2float(op[(size_t)ty * D_DIM + d0 + tx]);
    float xr1 = __half2float(xp[(size_t)(ty + 32) * D_DIM + d0 + tx]);
    float or1 = __half2float(op[(size_t)(ty + 32) * D_DIM + d0 + tx]);

    for (int s0 = 0; s0 < S_LEN; s0 += 64) {
        // publish prefetched tile
        xs[ty][tx]      = xr0;
        os[ty][tx]      = or0;
        xs[ty + 32][tx] = xr1;
        os[ty + 32][tx] = or1;
        __syncthreads();

        // issue next tile's loads early
        if (s0 + 64 < S_LEN) {
            const size_t nb0 = (size_t)(s0 + 64 + ty) * D_DIM + d0 + tx;
            const size_t nb1 = (size_t)(s0 + 96 + ty) * D_DIM + d0 + tx;
            xr0 = __half2float(xp[nb0]);
            or0 = __half2float(op[nb0]);
            xr1 = __half2float(xp[nb1]);
            or1 = __half2float(op[nb1]);
        }

        // scan phase: lane=tx is s-local, warp=ty is d-local; two chained halves
        #pragma unroll
        for (int half = 0; half < 2; half++) {
            const int sl = half * 32 + tx;
            const float pos = (float)(s0 + sl + 1);
            float w = os[sl][ty] * rsqrtf(pos);

            float pl = w;
            #pragma unroll
            for (int off = 1; off < 32; off <<= 1) {
                float t = __shfl_up_sync(0xffffffffu, pl, off);
                if (tx >= off) pl += t;
            }
            const float phi = c0 + pl;
            c0 += __shfl_sync(0xffffffffu, pl, 31);

            const float sv = __sinf(phi);
            const float cv = __cosf(phi);
            const float xv  = xs[sl][ty];
            const float cmr = xv * cv;
            const float cmi = xv * sv;

            float pr = cmr;
            #pragma unroll
            for (int off = 1; off < 32; off <<= 1) {
                float t = __shfl_up_sync(0xffffffffu, pr, off);
                if (tx >= off) pr += t;
            }
            float pi = cmi;
            #pragma unroll
            for (int off = 1; off < 32; off <<= 1) {
                float t = __shfl_up_sync(0xffffffffu, pi, off);
                if (tx >= off) pi += t;
            }

            const float ip = __fdividef(1.0f, pos);
            const float memr = (c1 + pr) * ip;
            const float memi = (c2 + pi) * ip;
            c1 += __shfl_sync(0xffffffffu, pr, 31);
            c2 += __shfl_sync(0xffffffffu, pi, 31);

            const float retr = memr * cv + memi * sv;
            const float reti = memi * cv - memr * sv;

            ob[0][sl][ty] = cmr;
            ob[1][sl][ty] = cmi;
            ob[2][sl][ty] = retr;
            ob[3][sl][ty] = reti;
        }
        __syncthreads();

        // store phase: thread (tx=d-local=lane, ty=s-local=warp), rows ty & ty+32
        #pragma unroll
        for (int half = 0; half < 2; half++) {
            const int r = half * 32 + ty;
            const float v0 = ob[0][r][tx];
            const float v1 = ob[1][r][tx];
            const float v2 = ob[2][r][tx];
            const float v3 = ob[3][r][tx];
            const size_t ro = (size_t)(s0 + r) * FD + d0 + tx;
            cp[ro]             = __float2half(v0);
            cp[ro + D_DIM]     = __float2half(v1);
            cp[ro + 2 * D_DIM] = __float2half(v2);
            cp[ro + 3 * D_DIM] = __float2half(v3);

            float ls  = v0 + v1 + v2 + v3;
            float ls2 = v0 * v0 + v1 * v1 + v2 * v2 + v3 * v3;
            #pragma unroll
            for (int off = 16; off > 0; off >>= 1) {
                ls  += __shfl_down_sync(0xffffffffu, ls,  off);
                ls2 += __shfl_down_sync(0xffffffffu, ls2, off);
            }
            if (tx == 0) {
                const size_t pidx = (size_t)dblk * NROWS + rowbase + s0 + r;
                rs [pidx] = ls;
                rs2[pidx] = ls2;
            }
        }
        // no trailing barrier: next iteration's xs/os writes are ordered after
        // this iteration's ob-phase barrier; ob reads complete before the next
        // iteration's first barrier allows new ob writes.
    }
}

// ---------------------------------------------------------------------------
extern "C" void kernel_launch(void* const* d_in, const int* in_sizes, int n_in,
                              void* d_out, int out_size)
{
    const float* x         = (const float*)d_in[0];
    const float* W_omega   = (const float*)d_in[1];
    const float* b_omega   = (const float*)d_in[2];
    const float* log_scale = (const float*)d_in[3];
    const float* ln_gamma  = (const float*)d_in[4];
    const float* ln_beta   = (const float*)d_in[5];
    const float* W1        = (const float*)d_in[6];
    const float* b1        = (const float*)d_in[7];
    const float* W2        = (const float*)d_in[8];
    const float* b2        = (const float*)d_in[9];
    float* out = (float*)d_out;

    __half *xf, *w0f, *omega_p, *cf, *w1g, *w2f, *h1f;
    float *rs, *rs2, *mu, *inv, *r1, *r2, *e, *b0s;
    cudaGetSymbolAddress((void**)&xf,      g_xf);
    cudaGetSymbolAddress((void**)&w0f,     g_w0f);
    cudaGetSymbolAddress((void**)&omega_p, g_omega);
    cudaGetSymbolAddress((void**)&cf,      g_cf);
    cudaGetSymbolAddress((void**)&w1g,     g_w1g);
    cudaGetSymbolAddress((void**)&w2f,     g_w2f);
    cudaGetSymbolAddress((void**)&h1f,     g_h1f);
    cudaGetSymbolAddress((void**)&rs,      g_rs);
    cudaGetSymbolAddress((void**)&rs2,     g_rs2);
    cudaGetSymbolAddress((void**)&mu,      g_mu);
    cudaGetSymbolAddress((void**)&inv,     g_inv);
    cudaGetSymbolAddress((void**)&r1,      g_r1);
    cudaGetSymbolAddress((void**)&r2,      g_r2);
    cudaGetSymbolAddress((void**)&e,       g_e);
    cudaGetSymbolAddress((void**)&b0s,     g_b0s);

    cudaFuncSetAttribute(gemm_f16_kernel<0>, cudaFuncAttributeMaxDynamicSharedMemorySize, GEMM_DSMF);
    cudaFuncSetAttribute(gemm_f16_kernel<1>, cudaFuncAttributeMaxDynamicSharedMemorySize, GEMM_DSMF);
    cudaFuncSetAttribute(gemm_f16_kernel<2>, cudaFuncAttributeMaxDynamicSharedMemorySize, GEMM_DSMF);

    // operand prep
    escale_kernel<<<(D_DIM + 255) / 256, 256>>>(log_scale, b_omega, e, b0s);
    prep_kernel<<<PREP_B3, 256>>>(x, W_omega, W1, W2, ln_gamma, e, xf, w0f, w1g, w2f);
    r12_kernel<<<HD / 8, dim3(32, 8)>>>(W1, ln_gamma, ln_beta, r1, r2);

    // 1) omega*e = x @ (W_omega*e)^T + b_omega*e   (fp16, f16 out)
    gemm_f16_kernel<0><<<dim3(D_DIM / 128, NROWS / 128), 256, GEMM_DSMF>>>(
        xf, w0f, b0s, nullptr, nullptr, nullptr, nullptr, nullptr,
        nullptr, omega_p, NROWS, D_DIM, D_DIM);

    // 2) scans -> raw ctx f16 + LN partial sums
    scan_kernel<<<dim3(NDBLK, B_DIM), dim3(32, 32)>>>(xf, omega_p, cf, rs, rs2);

    // 3) finalize per-row mu, inv
    rowstat_kernel<<<(NROWS + 255) / 256, 256>>>(rs, rs2, mu, inv);

    // 4) h1 = GELU(LN-affine(ctx @ (W1*gamma)^T)) -> f16   (LayerNorm fused)
    gemm_f16_kernel<1><<<dim3(HD / 128, NROWS / 128), 256, GEMM_DSMF>>>(
        cf, w1g, b1, nullptr, mu, inv, r1, r2,
        nullptr, h1f, NROWS, HD, FD);

    // 5) out = x + h1 @ W2^T + b2
    gemm_f16_kernel<2><<<dim3(D_DIM / 128, NROWS / 128), 256, GEMM_DSMF>>>(
        h1f, w2f, b2, x, nullptr, nullptr, nullptr, nullptr,
        out, nullptr, NROWS, D_DIM, HD);
}

// round 15
// speedup vs baseline: 1.0916x; 1.0200x over previous
#include <cuda_runtime.h>
#include <cuda_fp16.h>
#include <math.h>
#include <stdint.h>

// Shapes fixed: B=4, S=4096, D=1024
static constexpr int S_LEN = 4096;
static constexpr int D_DIM = 1024;
static constexpr int B_DIM = 4;
static constexpr int FD    = 4 * D_DIM;     // 4096
static constexpr int HD    = 2 * D_DIM;     // 2048
static constexpr int NROWS = B_DIM * S_LEN; // 16384
static constexpr int NDBLK = D_DIM / 32;    // 32 scan d-blocks

// ---------------- scratch (device globals; no allocs allowed) ----------------
__device__ __half g_xf  [(size_t)NROWS * D_DIM];   // 32 MB  x fp16
__device__ __half g_w0f [(size_t)D_DIM * D_DIM];   //  2 MB  W_omega*e fp16
__device__ __half g_omega[(size_t)NROWS * D_DIM];  // 32 MB  omega*e fp16
__device__ __half g_cf  [(size_t)NROWS * FD];      // 128 MB raw ctx fp16
__device__ __half g_w1g [(size_t)HD * FD];         // 16 MB  W1*gamma fp16
__device__ __half g_w2f [(size_t)D_DIM * HD];      //  4 MB  W2 fp16
__device__ __half g_h1f [(size_t)NROWS * HD];      // 64 MB  GELU output fp16
__device__ float  g_rs  [(size_t)NDBLK * NROWS];   //  2 MB  partial row sums
__device__ float  g_rs2 [(size_t)NDBLK * NROWS];   //  2 MB  partial row sumsq
__device__ float  g_mu  [NROWS];
__device__ float  g_inv [NROWS];
__device__ float  g_r1  [HD];                      // sum_d gamma*W1
__device__ float  g_r2  [HD];                      // sum_d beta*W1
__device__ float  g_e   [D_DIM];                   // exp(log_scale)
__device__ float  g_b0s [D_DIM];                   // b_omega * e

// ---------------- PTX helpers (stable ISA only) ----------------
__device__ __forceinline__ uint32_t smem_u32(const void* p) {
    uint32_t a;
    asm("{ .reg .u64 t; cvta.to.shared.u64 t, %1; cvt.u32.u64 %0, t; }" : "=r"(a) : "l"(p));
    return a;
}
__device__ __forceinline__ void cp_async16(uint32_t saddr, const void* gptr) {
    asm volatile("cp.async.cg.shared.global [%0], [%1], 16;" :: "r"(saddr), "l"(gptr));
}
__device__ __forceinline__ void cp_commit() { asm volatile("cp.async.commit_group;" ::: "memory"); }
template <int N> __device__ __forceinline__ void cp_wait() {
    asm volatile("cp.async.wait_group %0;" :: "n"(N) : "memory");
}

#define LDMX4(r0, r1, r2, r3, addr)                                              \
    asm volatile("ldmatrix.sync.aligned.m8n8.x4.shared.b16 {%0,%1,%2,%3}, [%4];" \
        : "=r"(r0), "=r"(r1), "=r"(r2), "=r"(r3) : "r"(addr))

#define MMA16816_F16(d, a, b0, b1)                                               \
    asm volatile("mma.sync.aligned.m16n8k16.row.col.f32.f16.f16.f32 "            \
        "{%0,%1,%2,%3}, {%4,%5,%6,%7}, {%8,%9}, {%0,%1,%2,%3};"                  \
        : "+f"((d)[0]), "+f"((d)[1]), "+f"((d)[2]), "+f"((d)[3])                 \
        : "r"((a)[0]), "r"((a)[1]), "r"((a)[2]), "r"((a)[3]), "r"(b0), "r"(b1))

// ===========================================================================
// fp16 GEMM (f32 accum): C[M,N] = A[M,K]*B[N,K]^T.  (best-measured config)
// 128x128 tile, BK=64, 3-stage cp.async, 256 thr (8 warps 2x4), warp 64x32.
// At the f32-acc HMMA roof (rt=16/SMSP): tensor=54% of ncu-normalized peak.
// EPI 0: + bias           -> f16 out            (GEMM1: omega)
// EPI 1: LN-affine + GELU -> f16 out            (GEMM2, fused LayerNorm)
// EPI 2: + bias + res     -> fp32 out           (GEMM3, residual)
// ===========================================================================
static constexpr int TILE_B    = 128 * 128;           // 16 KB f16 128x64 tile
static constexpr int STAGE_BF  = 2 * TILE_B;          // 32 KB
static constexpr int NSTAGEF   = 3;
static constexpr int GEMM_DSMF = NSTAGEF * STAGE_BF;  // 96 KB -> 2 CTAs/SM

template <int EPI>
__global__ __launch_bounds__(256, 2)
void gemm_f16_kernel(const __half* __restrict__ A, const __half* __restrict__ B,
                     const float* __restrict__ bias, const float* __restrict__ res,
                     const float* __restrict__ mu, const float* __restrict__ inv,
                     const float* __restrict__ r1, const float* __restrict__ r2,
                     float* __restrict__ outf, __half* __restrict__ outh,
                     int M, int N, int K)
{
    extern __shared__ __align__(1024) unsigned char dsm[];
    const int tid = threadIdx.x;
    const int wid = tid >> 5;
    const int lid = tid & 31;
    const int m0 = blockIdx.y * 128;
    const int n0 = blockIdx.x * 128;
    const uint32_t dsm_b = smem_u32(dsm);

    const int warpM = wid >> 2, warpN = wid & 3;
    const int rl = lid & 15, chh = lid >> 4;

    const __half* At = A + (size_t)m0 * K;
    const __half* Bt = B + (size_t)n0 * K;

    const int nchunk = K >> 6;

    auto load_chunk = [&](int chunk) {
        const uint32_t sb = dsm_b + (chunk % NSTAGEF) * STAGE_BF;
        const int koff = chunk << 6;
        #pragma unroll
        for (int i = 0; i < 8; i++) {
            const int u = i * 256 + tid;           // 0..2047
            const int t = u >> 10;                 // 0=A, 1=B
            const int v = u & 1023;
            const int row = v >> 3, c = v & 7;
            const __half* g = t ? Bt : At;
            const void* gp = g + (size_t)row * K + koff + c * 8;
            const uint32_t sa = sb + t * TILE_B + row * 128 + ((c ^ (row & 7)) << 4);
            cp_async16(sa, gp);
        }
        cp_commit();
    };

    float acc[4][4][4];
    #pragma unroll
    for (int mi = 0; mi < 4; mi++)
        #pragma unroll
        for (int ni = 0; ni < 4; ni++)
            #pragma unroll
            for (int r = 0; r < 4; r++) acc[mi][ni][r] = 0.0f;

    load_chunk(0);
    load_chunk(1);

    for (int c = 0; c < nchunk; c++) {
        if (c < nchunk - 1) cp_wait<1>(); else cp_wait<0>();
        __syncthreads();
        if (c + 2 < nchunk) load_chunk(c + 2);

        const uint32_t st = dsm_b + (c % NSTAGEF) * STAGE_BF;
        #pragma unroll
        for (int ks = 0; ks < 4; ks++) {
            const int kchunk = (ks << 1) | chh;
            uint32_t a[4][4], b[2][4];
            #pragma unroll
            for (int mi = 0; mi < 4; mi++) {
                const int row = warpM * 64 + mi * 16 + rl;
                const uint32_t ad = st + row * 128 + ((kchunk ^ (row & 7)) << 4);
                LDMX4(a[mi][0], a[mi][1], a[mi][2], a[mi][3], ad);
            }
            #pragma unroll
            for (int nj = 0; nj < 2; nj++) {
                const int row = warpN * 32 + nj * 16 + rl;
                const uint32_t bd = st + TILE_B + row * 128 + ((kchunk ^ (row & 7)) << 4);
                LDMX4(b[nj][0], b[nj][1], b[nj][2], b[nj][3], bd);
            }
            #pragma unroll
            for (int mi = 0; mi < 4; mi++)
                #pragma unroll
                for (int ni = 0; ni < 4; ni++) {
                    const int nj = ni >> 1, sel = ni & 1;
                    MMA16816_F16(acc[mi][ni], a[mi], b[nj][sel], b[nj][2 + sel]);
                }
        }
    }

    const int g = lid >> 2, q = lid & 3;
    #pragma unroll
    for (int mi = 0; mi < 4; mi++)
        #pragma unroll
        for (int ni = 0; ni < 4; ni++) {
            const int row = m0 + warpM * 64 + mi * 16 + g;
            const int col = n0 + warpN * 32 + ni * 8 + q * 2;
            const size_t o0 = (size_t)row * N + col;
            const size_t o1 = (size_t)(row + 8) * N + col;
            float v[4];
            if (EPI == 1) {
                // fused LayerNorm affine: inv*acc - inv*mu*r1[n] + r2[n] + bias[n]
                const float2 rr1 = *(const float2*)(r1 + col);
                const float2 rr2 = *(const float2*)(r2 + col);
                const float2 bb  = *(const float2*)(bias + col);
                const float i0 = inv[row],     m0v = mu[row];
                const float i1 = inv[row + 8], m1v = mu[row + 8];
                v[0] = i0 * acc[mi][ni][0] - i0 * m0v * rr1.x + rr2.x + bb.x;
                v[1] = i0 * acc[mi][ni][1] - i0 * m0v * rr1.y + rr2.y + bb.y;
                v[2] = i1 * acc[mi][ni][2] - i1 * m1v * rr1.x + rr2.x + bb.x;
                v[3] = i1 * acc[mi][ni][3] - i1 * m1v * rr1.y + rr2.y + bb.y;
                #pragma unroll
                for (int r = 0; r < 4; r++)
                    v[r] = 0.5f * v[r] * (1.0f + erff(v[r] * 0.70710678118654752f));
                *(__half2*)(outh + o0) = __floats2half2_rn(v[0], v[1]);
                *(__half2*)(outh + o1) = __floats2half2_rn(v[2], v[3]);
            } else {
                const float2 bb = *(const float2*)(bias + col);
                v[0] = acc[mi][ni][0] + bb.x;
                v[1] = acc[mi][ni][1] + bb.y;
                v[2] = acc[mi][ni][2] + bb.x;
                v[3] = acc[mi][ni][3] + bb.y;
                if (EPI == 2) {
                    const float2 q0 = *(const float2*)(res + o0);
                    const float2 q1 = *(const float2*)(res + o1);
                    *(float2*)(outf + o0) = make_float2(v[0] + q0.x, v[1] + q0.y);
                    *(float2*)(outf + o1) = make_float2(v[2] + q1.x, v[3] + q1.y);
                } else {
                    *(__half2*)(outh + o0) = __floats2half2_rn(v[0], v[1]);
                    *(__half2*)(outh + o1) = __floats2half2_rn(v[2], v[3]);
                }
            }
        }
}

// ---------------------------------------------------------------------------
// escale: e = exp(log_scale), b0s = b_omega * e
// ---------------------------------------------------------------------------
__global__ __launch_bounds__(256)
void escale_kernel(const float* __restrict__ log_scale, const float* __restrict__ b0,
                   float* __restrict__ e, float* __restrict__ b0s)
{
    const int i = blockIdx.x * blockDim.x + threadIdx.x;
    if (i >= D_DIM) return;
    const float ev = expf(log_scale[i]);
    e[i] = ev;
    b0s[i] = b0[i] * ev;
}

// ---------------------------------------------------------------------------
// Fused operand prep (segments): x->xf | W0*e->w0f | W1*gamma->w1g | W2->w2f
// ---------------------------------------------------------------------------
static constexpr int PREP_B0 = NROWS * D_DIM / 1024;                 // 16384
static constexpr int PREP_B1 = PREP_B0 + D_DIM * D_DIM / 1024;       // +1024
static constexpr int PREP_B2 = PREP_B1 + HD * FD / 1024;             // +8192
static constexpr int PREP_B3 = PREP_B2 + D_DIM * HD / 1024;          // +2048

__global__ __launch_bounds__(256)
void prep_kernel(const float* __restrict__ x, const float* __restrict__ W0,
                 const float* __restrict__ W1, const float* __restrict__ W2,
                 const float* __restrict__ gamma, const float* __restrict__ e,
                 __half* __restrict__ xf, __half* __restrict__ w0f,
                 __half* __restrict__ w1g, __half* __restrict__ w2f)
{
    const int blk = blockIdx.x;
    const int tid = threadIdx.x;
    if (blk < PREP_B0) {
        const size_t i = (size_t)blk * 256 + tid;     // float4 index
        const float4 v = ((const float4*)x)[i];
        __half2* op = (__half2*)xf;
        op[2 * i]     = __floats2half2_rn(v.x, v.y);
        op[2 * i + 1] = __floats2half2_rn(v.z, v.w);
    } else if (blk < PREP_B1) {
        const size_t i = (size_t)(blk - PREP_B0) * 256 + tid;
        const int n = (int)((i * 4) >> 10);           // row (K=1024 fast)
        const float ev = e[n];
        const float4 v = ((const float4*)W0)[i];
        __half2* op = (__half2*)w0f;
        op[2 * i]     = __floats2half2_rn(v.x * ev, v.y * ev);
        op[2 * i + 1] = __floats2half2_rn(v.z * ev, v.w * ev);
    } else if (blk < PREP_B2) {
        const size_t i = (size_t)(blk - PREP_B1) * 256 + tid;
        const int d = (int)((i * 4) & (FD - 1));
        const float4 v = ((const float4*)W1)[i];
        const float4 gg = *(const float4*)(gamma + d);
        __half2* op = (__half2*)w1g;
        op[2 * i]     = __floats2half2_rn(v.x * gg.x, v.y * gg.y);
        op[2 * i + 1] = __floats2half2_rn(v.z * gg.z, v.w * gg.w);
    } else {
        const size_t i = (size_t)(blk - PREP_B2) * 256 + tid;
        const float4 v = ((const float4*)W2)[i];
        __half2* op = (__half2*)w2f;
        op[2 * i]     = __floats2half2_rn(v.x, v.y);
        op[2 * i + 1] = __floats2half2_rn(v.z, v.w);
    }
}

// r1[n] = sum_d gamma[d]*W1[n,d];  r2[n] = sum_d beta[d]*W1[n,d]. One warp per n.
__global__ __launch_bounds__(256)
void r12_kernel(const float* __restrict__ W1, const float* __restrict__ gamma,
                const float* __restrict__ beta, float* __restrict__ r1,
                float* __restrict__ r2)
{
    const int n = blockIdx.x * 8 + threadIdx.y;
    const int lane = threadIdx.x;
    const float* wr = W1 + (size_t)n * FD;
    float a = 0.0f, b = 0.0f;
    for (int d = lane * 4; d < FD; d += 128) {
        const float4 w = *(const float4*)(wr + d);
        const float4 gg = *(const float4*)(gamma + d);
        const float4 be = *(const float4*)(beta + d);
        a += w.x * gg.x + w.y * gg.y + w.z * gg.z + w.w * gg.w;
        b += w.x * be.x + w.y * be.y + w.z * be.z + w.w * be.w;
    }
    #pragma unroll
    for (int off = 16; off > 0; off >>= 1) {
        a += __shfl_down_sync(0xffffffffu, a, off);
        b += __shfl_down_sync(0xffffffffu, b, off);
    }
    if (lane == 0) { r1[n] = a; r2[n] = b; }
}

// finalize per-row LN stats from 32 deterministic partials
__global__ __launch_bounds__(256)
void rowstat_kernel(const float* __restrict__ rs, const float* __restrict__ rs2,
                    float* __restrict__ mu, float* __restrict__ inv)
{
    const int r = blockIdx.x * blockDim.x + threadIdx.x;
    if (r >= NROWS) return;
    float s1 = 0.0f, s2 = 0.0f;
    #pragma unroll
    for (int j = 0; j < NDBLK; j++) {
        s1 += rs [(size_t)j * NROWS + r];
        s2 += rs2[(size_t)j * NROWS + r];
    }
    const float m = s1 * (1.0f / FD);
    mu[r]  = m;
    inv[r] = rsqrtf(s2 * (1.0f / FD) - m * m + 1e-5f);
}

// ---------------------------------------------------------------------------
// Fused sequential scans -> raw ctx fp16 + deterministic per-row partial sums.
// STILE=128: four chained 32-lane warp scans per iteration (carries forwarded
// in registers, bitwise-identical order) -> 32 iterations, quarter the barriers
// of the original. Dynamic smem (~101 KB), 1 CTA/SM, 128 blocks.
// ---------------------------------------------------------------------------
static constexpr int STILE = 128;
static constexpr int SCAN_NIT = S_LEN / STILE;           // 32
// dynamic smem layout (floats): xs[128][33] | os[128][33] | ob[4][128][33]
static constexpr int SC_ROW   = 33;
static constexpr int SC_XS    = 0;
static constexpr int SC_OS    = SC_XS + STILE * SC_ROW;
static constexpr int SC_OB    = SC_OS + STILE * SC_ROW;
static constexpr int SCAN_DSM = (SC_OB + 4 * STILE * SC_ROW) * 4;  // bytes

__global__ __launch_bounds__(1024, 1)
void scan_kernel(const __half* __restrict__ xf, const __half* __restrict__ omega,
                 __half* __restrict__ ctx,
                 float* __restrict__ rs, float* __restrict__ rs2)
{
    extern __shared__ float sms[];
    float* xs = sms + SC_XS;                  // [STILE][33]
    float* os = sms + SC_OS;                  // [STILE][33]
    float* ob = sms + SC_OB;                  // [4][STILE][33]

    const int b  = blockIdx.y;
    const int dblk = blockIdx.x;
    const int d0 = dblk * 32;
    const int tx = threadIdx.x;
    const int ty = threadIdx.y;

    const __half* xp = xf    + (size_t)b * S_LEN * D_DIM;
    const __half* op = omega + (size_t)b * S_LEN * D_DIM;
    __half*      cp = ctx   + (size_t)b * S_LEN * FD;
    const int rowbase = b * S_LEN;

    float c0 = 0.0f, c1 = 0.0f, c2 = 0.0f;

    // prefetch tile 0 (rows ty + 32*j, j=0..3)
    float xr[4], orr[4];
    #pragma unroll
    for (int j = 0; j < 4; j++) {
        const size_t a0 = (size_t)(ty + 32 * j) * D_DIM + d0 + tx;
        xr[j]  = __half2float(xp[a0]);
        orr[j] = __half2float(op[a0]);
    }

    for (int s0 = 0; s0 < S_LEN; s0 += STILE) {
        // publish prefetched tile
        #pragma unroll
        for (int j = 0; j < 4; j++) {
            xs[(ty + 32 * j) * SC_ROW + tx] = xr[j];
            os[(ty + 32 * j) * SC_ROW + tx] = orr[j];
        }
        __syncthreads();

        // issue next tile's loads early
        if (s0 + STILE < S_LEN) {
            #pragma unroll
            for (int j = 0; j < 4; j++) {
                const size_t nb = (size_t)(s0 + STILE + ty + 32 * j) * D_DIM + d0 + tx;
                xr[j]  = __half2float(xp[nb]);
                orr[j] = __half2float(op[nb]);
            }
        }

        // scan phase: lane=tx is s-local, warp=ty is d-local; four chained quarters
        #pragma unroll
        for (int half = 0; half < 4; half++) {
            const int sl = half * 32 + tx;
            const float pos = (float)(s0 + sl + 1);
            float w = os[sl * SC_ROW + ty] * rsqrtf(pos);

            float pl = w;
            #pragma unroll
            for (int off = 1; off < 32; off <<= 1) {
                float t = __shfl_up_sync(0xffffffffu, pl, off);
                if (tx >= off) pl += t;
            }
            const float phi = c0 + pl;
            c0 += __shfl_sync(0xffffffffu, pl, 31);

            const float sv = __sinf(phi);
            const float cv = __cosf(phi);
            const float xv  = xs[sl * SC_ROW + ty];
            const float cmr = xv * cv;
            const float cmi = xv * sv;

            float pr = cmr;
            #pragma unroll
            for (int off = 1; off < 32; off <<= 1) {
                float t = __shfl_up_sync(0xffffffffu, pr, off);
                if (tx >= off) pr += t;
            }
            float pi = cmi;
            #pragma unroll
            for (int off = 1; off < 32; off <<= 1) {
                float t = __shfl_up_sync(0xffffffffu, pi, off);
                if (tx >= off) pi += t;
            }

            const float ip = __fdividef(1.0f, pos);
            const float memr = (c1 + pr) * ip;
            const float memi = (c2 + pi) * ip;
            c1 += __shfl_sync(0xffffffffu, pr, 31);
            c2 += __shfl_sync(0xffffffffu, pi, 31);

            const float retr = memr * cv + memi * sv;
            const float reti = memi * cv - memr * sv;

            ob[(0 * STILE + sl) * SC_ROW + ty] = cmr;
            ob[(1 * STILE + sl) * SC_ROW + ty] = cmi;
            ob[(2 * STILE + sl) * SC_ROW + ty] = retr;
            ob[(3 * STILE + sl) * SC_ROW + ty] = reti;
        }
        __syncthreads();

        // store phase: thread (tx=d-local=lane, ty=s-local=warp), rows ty + 32*j
        #pragma unroll
        for (int half = 0; half < 4; half++) {
            const int r = half * 32 + ty;
            const float v0 = ob[(0 * STILE + r) * SC_ROW + tx];
            const float v1 = ob[(1 * STILE + r) * SC_ROW + tx];
            const float v2 = ob[(2 * STILE + r) * SC_ROW + tx];
            const float v3 = ob[(3 * STILE + r) * SC_ROW + tx];
            const size_t ro = (size_t)(s0 + r) * FD + d0 + tx;
            cp[ro]             = __float2half(v0);
            cp[ro + D_DIM]     = __float2half(v1);
            cp[ro + 2 * D_DIM] = __float2half(v2);
            cp[ro + 3 * D_DIM] = __float2half(v3);

            float ls  = v0 + v1 + v2 + v3;
            float ls2 = v0 * v0 + v1 * v1 + v2 * v2 + v3 * v3;
            #pragma unroll
            for (int off = 16; off > 0; off >>= 1) {
                ls  += __shfl_down_sync(0xffffffffu, ls,  off);
                ls2 += __shfl_down_sync(0xffffffffu, ls2, off);
            }
            if (tx == 0) {
                const size_t pidx = (size_t)dblk * NROWS + rowbase + s0 + r;
                rs [pidx] = ls;
                rs2[pidx] = ls2;
            }
        }
        // no trailing barrier: next iteration's xs/os writes are ordered after
        // this iteration's ob-phase barrier; ob reads complete before the next
        // iteration's first barrier allows new ob writes.
    }
}

// ---------------------------------------------------------------------------
extern "C" void kernel_launch(void* const* d_in, const int* in_sizes, int n_in,
                              void* d_out, int out_size)
{
    const float* x         = (const float*)d_in[0];
    const float* W_omega   = (const float*)d_in[1];
    const float* b_omega   = (const float*)d_in[2];
    const float* log_scale = (const float*)d_in[3];
    const float* ln_gamma  = (const float*)d_in[4];
    const float* ln_beta   = (const float*)d_in[5];
    const float* W1        = (const float*)d_in[6];
    const float* b1        = (const float*)d_in[7];
    const float* W2        = (const float*)d_in[8];
    const float* b2        = (const float*)d_in[9];
    float* out = (float*)d_out;

    __half *xf, *w0f, *omega_p, *cf, *w1g, *w2f, *h1f;
    float *rs, *rs2, *mu, *inv, *r1, *r2, *e, *b0s;
    cudaGetSymbolAddress((void**)&xf,      g_xf);
    cudaGetSymbolAddress((void**)&w0f,     g_w0f);
    cudaGetSymbolAddress((void**)&omega_p, g_omega);
    cudaGetSymbolAddress((void**)&cf,      g_cf);
    cudaGetSymbolAddress((void**)&w1g,     g_w1g);
    cudaGetSymbolAddress((void**)&w2f,     g_w2f);
    cudaGetSymbolAddress((void**)&h1f,     g_h1f);
    cudaGetSymbolAddress((void**)&rs,      g_rs);
    cudaGetSymbolAddress((void**)&rs2,     g_rs2);
    cudaGetSymbolAddress((void**)&mu,      g_mu);
    cudaGetSymbolAddress((void**)&inv,     g_inv);
    cudaGetSymbolAddress((void**)&r1,      g_r1);
    cudaGetSymbolAddress((void**)&r2,      g_r2);
    cudaGetSymbolAddress((void**)&e,       g_e);
    cudaGetSymbolAddress((void**)&b0s,     g_b0s);

    cudaFuncSetAttribute(gemm_f16_kernel<0>, cudaFuncAttributeMaxDynamicSharedMemorySize, GEMM_DSMF);
    cudaFuncSetAttribute(gemm_f16_kernel<1>, cudaFuncAttributeMaxDynamicSharedMemorySize, GEMM_DSMF);
    cudaFuncSetAttribute(gemm_f16_kernel<2>, cudaFuncAttributeMaxDynamicSharedMemorySize, GEMM_DSMF);
    cudaFuncSetAttribute(scan_kernel, cudaFuncAttributeMaxDynamicSharedMemorySize, SCAN_DSM);

    // operand prep
    escale_kernel<<<(D_DIM + 255) / 256, 256>>>(log_scale, b_omega, e, b0s);
    prep_kernel<<<PREP_B3, 256>>>(x, W_omega, W1, W2, ln_gamma, e, xf, w0f, w1g, w2f);
    r12_kernel<<<HD / 8, dim3(32, 8)>>>(W1, ln_gamma, ln_beta, r1, r2);

    // 1) omega*e = x @ (W_omega*e)^T + b_omega*e   (fp16, f16 out)
    gemm_f16_kernel<0><<<dim3(D_DIM / 128, NROWS / 128), 256, GEMM_DSMF>>>(
        xf, w0f, b0s, nullptr, nullptr, nullptr, nullptr, nullptr,
        nullptr, omega_p, NROWS, D_DIM, D_DIM);

    // 2) scans -> raw ctx f16 + LN partial sums
    scan_kernel<<<dim3(NDBLK, B_DIM), dim3(32, 32), SCAN_DSM>>>(xf, omega_p, cf, rs, rs2);

    // 3) finalize per-row mu, inv
    rowstat_kernel<<<(NROWS + 255) / 256, 256>>>(rs, rs2, mu, inv);

    // 4) h1 = GELU(LN-affine(ctx @ (W1*gamma)^T)) -> f16   (LayerNorm fused)
    gemm_f16_kernel<1><<<dim3(HD / 128, NROWS / 128), 256, GEMM_DSMF>>>(
        cf, w1g, b1, nullptr, mu, inv, r1, r2,
        nullptr, h1f, NROWS, HD, FD);

    // 5) out = x + h1 @ W2^T + b2
    gemm_f16_kernel<2><<<dim3(D_DIM / 128, NROWS / 128), 256, GEMM_DSMF>>>(
        h1f, w2f, b2, x, nullptr, nullptr, nullptr, nullptr,
        out, nullptr, NROWS, D_DIM, HD);
}